// round 11
// baseline (speedup 1.0000x reference)
#include <cuda_runtime.h>
#include <cuda_bf16.h>
#include <math.h>

#define BB 8
#define C 64
#define H 128
#define W 128
#define HW (H*W)            // 16384
#define NPIX (BB*HW)        // 131072
#define CO_OFF 27
#define KIDX 576
#define NTILE 1024          // 128 px per tile (one image row)

typedef unsigned long long u64;

// ---------------- packed fp32x2 helpers ----------------
__device__ __forceinline__ u64 pk(float x, float y) {
    u64 r; asm("mov.b64 %0, {%1, %2};" : "=l"(r) : "f"(x), "f"(y)); return r;
}
__device__ __forceinline__ float2 upk(u64 a) {
    float2 f; asm("mov.b64 {%0, %1}, %2;" : "=f"(f.x), "=f"(f.y) : "l"(a)); return f;
}
__device__ __forceinline__ u64 ffma2(u64 a, u64 b, u64 c) {
    u64 d; asm("fma.rn.f32x2 %0, %1, %2, %3;" : "=l"(d) : "l"(a), "l"(b), "l"(c)); return d;
}
__device__ __forceinline__ u64 fmul2(u64 a, u64 b) {
    u64 d; asm("mul.rn.f32x2 %0, %1, %2;" : "=l"(d) : "l"(a), "l"(b)); return d;
}
// bf16x2 pack: x -> low half, y -> high half
__device__ __forceinline__ unsigned bf16x2_of(float x, float y) {
    unsigned r; asm("cvt.rn.satfinite.bf16x2.f32 %0, %1, %2;" : "=r"(r) : "f"(y), "f"(x)); return r;
}

// ---------------- mma.sync / ldmatrix (baseline PTX) ----------------
__device__ __forceinline__ void ldsm_x4(unsigned& r0, unsigned& r1, unsigned& r2, unsigned& r3,
                                        unsigned addr) {
    asm volatile("ldmatrix.sync.aligned.m8n8.x4.shared.b16 {%0,%1,%2,%3}, [%4];"
        : "=r"(r0), "=r"(r1), "=r"(r2), "=r"(r3) : "r"(addr));
}
__device__ __forceinline__ void ldsm_x4t(unsigned& r0, unsigned& r1, unsigned& r2, unsigned& r3,
                                         unsigned addr) {
    asm volatile("ldmatrix.sync.aligned.m8n8.x4.trans.shared.b16 {%0,%1,%2,%3}, [%4];"
        : "=r"(r0), "=r"(r1), "=r"(r2), "=r"(r3) : "r"(addr));
}
__device__ __forceinline__ void mma16816(float* c,
                                         unsigned a0, unsigned a1, unsigned a2, unsigned a3,
                                         unsigned b0, unsigned b1) {
    asm volatile(
        "mma.sync.aligned.m16n8k16.row.col.f32.bf16.bf16.f32 "
        "{%0,%1,%2,%3}, {%4,%5,%6,%7}, {%8,%9}, {%0,%1,%2,%3};"
        : "+f"(c[0]), "+f"(c[1]), "+f"(c[2]), "+f"(c[3])
        : "r"(a0), "r"(a1), "r"(a2), "r"(a3), "r"(b0), "r"(b1));
}
__device__ __forceinline__ unsigned smem_u32(const void* p) {
    unsigned a; asm("{ .reg .u64 t; cvta.to.shared.u64 t, %1; cvt.u32.u64 %0, t; }" : "=r"(a) : "l"(p));
    return a;
}
#define MBAR_INIT(mb, n) asm volatile("mbarrier.init.shared.b64 [%0], %1;" :: "r"(mb), "r"(n) : "memory")
#define MBAR_ARRIVE(mb)  asm volatile("mbarrier.arrive.shared.b64 _, [%0];" :: "r"(mb) : "memory")
#define MBAR_WAIT(mb, ph) do { \
    unsigned _mb = (mb), _ph = (ph), _done; \
    asm volatile("{ .reg .pred p; mbarrier.try_wait.parity.acquire.cta.shared::cta.b64 p, [%1], %2; selp.b32 %0, 1, 0, p; }" \
        : "=r"(_done) : "r"(_mb), "r"(_ph) : "memory"); \
    if (!_done) { \
        asm volatile("{ .reg .pred P1; WL_%=: mbarrier.try_wait.parity.acquire.cta.shared::cta.b64 P1, [%0], %1, 0x989680; @P1 bra.uni WD_%=; bra.uni WL_%=; WD_%=: }" \
            :: "r"(_mb), "r"(_ph) : "memory"); \
    } } while (0)
#define CP_ASYNC16(dst, src) \
    asm volatile("cp.async.ca.shared.global [%0], [%1], 16;" :: "r"(dst), "l"(src) : "memory")
#define CP_COMMIT()  asm volatile("cp.async.commit_group;" ::: "memory")
#define CP_WAIT0()   asm volatile("cp.async.wait_group 0;" ::: "memory")

// ---------------- scratch ----------------
__device__ float g_xT[NPIX*C];                            // x NHWC
__device__ float g_off[BB*CO_OFF*HW];                     // offset conv out
__device__ __align__(16) unsigned short g_wB[9*2*64*64];  // W hi/lo, ldmatrix-ready blocks

// ---------------- NCHW -> NHWC transpose of x ----------------
__global__ void k_transpose_in(const float* __restrict__ x) {
    __shared__ float tile[32][33];
    int b  = blockIdx.z;
    int c0 = blockIdx.y * 32;
    int p0 = blockIdx.x * 32;
    int tx = threadIdx.x, ty = threadIdx.y;
#pragma unroll
    for (int i = 0; i < 4; i++)
        tile[ty + 8*i][tx] = x[(b*C + c0 + ty + 8*i)*HW + p0 + tx];
    __syncthreads();
#pragma unroll
    for (int i = 0; i < 4; i++)
        g_xT[(b*HW + p0 + ty + 8*i)*C + c0 + tx] = tile[tx][ty + 8*i];
}

// ---------------- prep: W -> bf16 hi/lo ldmatrix blocks ----------------
__global__ void k_wprep(const float* __restrict__ w_conv) {
    int i = blockIdx.x * blockDim.x + threadIdx.x;
    if (i >= 9*2*64*64) return;
    int o  = i & 63;
    int ch = (i >> 6) & 63;
    int hl = (i >> 12) & 1;
    int k  = i >> 13;
    float w = w_conv[o*KIDX + ch*9 + k];
    __nv_bfloat16 hi = __float2bfloat16(w);
    unsigned short val;
    if (hl == 0) {
        val = *(unsigned short*)&hi;
    } else {
        float fhi = __bfloat162float(hi);
        __nv_bfloat16 lo = __float2bfloat16(w - fhi);
        val = *(unsigned short*)&lo;
    }
    unsigned block = (unsigned)(((k*2 + hl)*16) + (ch >> 4)*4 + (o >> 4));
    unsigned inner = (unsigned)((ch & 15)*32 + (o & 15)*2);
    inner ^= ((inner >> 7) & 1) << 4;
    *(unsigned short*)((char*)g_wB + block*512 + inner) = val;
}

// ---------------- offset-predictor 3x3 conv, pad 1, 2 px/thread ----------------
__global__ __launch_bounds__(256) void k_offconv(
    const float* __restrict__ x, const float* __restrict__ w_off,
    const float* __restrict__ b_off)
{
    extern __shared__ float sw[];   // [576][28]
    for (int i = threadIdx.x; i < CO_OFF*KIDX; i += blockDim.x) {
        int co = i / KIDX;
        int r  = i - co*KIDX;
        sw[r*28 + co] = w_off[i];
    }
    __syncthreads();

    int pix0 = blockIdx.x * 512 + threadIdx.x;
    int b  = pix0 >> 14;
    int h0 = (pix0 >> 7) & 127;
    int w0 = pix0 & 127;
    int h1 = h0 + 2;

    int   off[9];
    float vm0[9], vm1[9];
#pragma unroll
    for (int t = 0; t < 9; t++) {
        int dy = t/3 - 1, dx = t%3 - 1;
        off[t] = dy*W + dx;
        int xx = w0 + dx;
        bool vx = (xx >= 0) && (xx < W);
        int y0 = h0 + dy, y1 = h1 + dy;
        vm0[t] = (vx && y0 >= 0 && y0 < H) ? 1.f : 0.f;
        vm1[t] = (vx && y1 >= 0 && y1 < H) ? 1.f : 0.f;
    }

    u64 acc0[14], acc1[14];
#pragma unroll
    for (int j = 0; j < 13; j++) { acc0[j] = pk(b_off[2*j], b_off[2*j+1]); acc1[j] = acc0[j]; }
    acc0[13] = pk(b_off[26], 0.f); acc1[13] = acc0[13];

    const float* xc0 = x + (size_t)b*C*HW + h0*W + w0;
    const float* xc1 = xc0 + 2*W;
#pragma unroll 1
    for (int c = 0; c < C; c++) {
        float xv0[9], xv1[9];
#pragma unroll
        for (int t = 0; t < 9; t++) {
            xv0[t] = vm0[t] * __ldg(xc0 + off[t]);
            xv1[t] = vm1[t] * __ldg(xc1 + off[t]);
        }
        const float* wp = sw + c*9*28;
#pragma unroll
        for (int t = 0; t < 9; t++) {
            u64 s0 = pk(xv0[t], xv0[t]);
            u64 s1 = pk(xv1[t], xv1[t]);
#pragma unroll
            for (int j = 0; j < 7; j++) {
                float4 w4 = *(const float4*)(wp + t*28 + 4*j);
                u64 wA = pk(w4.x, w4.y);
                u64 wB = pk(w4.z, w4.w);
                acc0[2*j]   = ffma2(s0, wA, acc0[2*j]);
                acc0[2*j+1] = ffma2(s0, wB, acc0[2*j+1]);
                acc1[2*j]   = ffma2(s1, wA, acc1[2*j]);
                acc1[2*j+1] = ffma2(s1, wB, acc1[2*j+1]);
            }
        }
        xc0 += HW; xc1 += HW;
    }
    float* op0 = g_off + (size_t)b*CO_OFF*HW + h0*W + w0;
    float* op1 = op0 + 2*W;
#pragma unroll
    for (int j = 0; j < 13; j++) {
        float2 a = upk(acc0[j]); float2 bq = upk(acc1[j]);
        op0[(2*j)*HW] = a.x;  op0[(2*j+1)*HW] = a.y;
        op1[(2*j)*HW] = bq.x; op1[(2*j+1)*HW] = bq.y;
    }
    op0[26*HW] = upk(acc0[13]).x;
    op1[26*HW] = upk(acc1[13]).x;
}

// ---------------- fused: 12 producer warps / 4 consumer warps ----------------
// smem:
//   [0..65536)      A ring, 2 stages x (hi 16KB + lo 16KB)
//   [65536..98304)  B ring, 2 slots x 16KB (one tap: hi 8KB + lo 8KB), cp.async-streamed
//   [98304..98336)  mbarriers: {full0, empty0, full1, empty1}
#define SMA   0
#define SMBR  65536
#define SMQ   98304
#define SMTOT 98368

__global__ __launch_bounds__(512, 1) void k_fused_ws(float* __restrict__ out) {
    extern __shared__ char sm[];
    const unsigned sb = smem_u32(sm);
    const int tid  = threadIdx.x;
    const int lane = tid & 31;
    const int warp = tid >> 5;

    if (tid == 0) {
        MBAR_INIT(sb + SMQ + 0,  384);   // full0  (12 producer warps arrive)
        MBAR_INIT(sb + SMQ + 8,  128);   // empty0 (4 consumer warps arrive)
        MBAR_INIT(sb + SMQ + 16, 384);   // full1
        MBAR_INIT(sb + SMQ + 24, 128);   // empty1
    }
    __syncthreads();

    int stage = 0;

    if (warp < 12) {
        // ================= PRODUCER (12 warps; warp w owns px {w + 12*i}) ====
        int ph = 1;
        const float2* xp2 = (const float2*)g_xT;
        const int wx = warp + 12*lane;                  // this lane's param px
        const bool pvalid = (lane < 11) && (wx < 128);

        for (int t = blockIdx.x; t < NTILE; t += gridDim.x) {
            const int b  = t >> 7;
            const int h  = t & 127;
            const int rb = b * HW;
            const int obase0 = b*CO_OFF*HW + h*W + wx;

            float no1 = 0.f, no2 = 0.f, nmv = 0.f;
            if (pvalid) {
                no1 = __ldg(g_off + obase0);
                no2 = __ldg(g_off + obase0 +  9*HW);
                nmv = __ldg(g_off + obase0 + 18*HW);
            }

#pragma unroll 1
            for (int k = 0; k < 9; k++) {
                float o1 = no1, o2 = no2, mv = nmv;
                if (k < 8 && pvalid) {
                    int ob = obase0 + (k+1)*HW;
                    no1 = __ldg(g_off + ob);
                    no2 = __ldg(g_off + ob +  9*HW);
                    nmv = __ldg(g_off + ob + 18*HW);
                }

                // per-lane params for px = wx (garbage-safe for invalid lanes:
                // o1/o2/mv default 0, coords clamp in-range, never shfl-sourced)
                float4 wt; int4 ix;
                {
                    float mask = 1.f / (1.f + expf(-mv));
                    int kh = k / 3;
                    int kw = k - kh*3;
                    float px = o1 + (float)(wx + kw - 1);
                    float py = o2 + (float)(h + kh - 1);
                    float x0f = floorf(px), y0f = floorf(py);
                    int x0 = (int)x0f, y0 = (int)y0f;
                    float wx1 = px - x0f, wy1 = py - y0f;
                    float wx0 = 1.f - wx1, wy0 = 1.f - wy1;
                    float vx0 = (x0 >= 0  && x0     < W) ? 1.f : 0.f;
                    float vx1 = (x0 >= -1 && x0 + 1 < W) ? 1.f : 0.f;
                    float vy0 = (y0 >= 0  && y0     < H) ? 1.f : 0.f;
                    float vy1 = (y0 >= -1 && y0 + 1 < H) ? 1.f : 0.f;
                    int cx0 = min(max(x0,   0), W-1);
                    int cx1 = min(max(x0+1, 0), W-1);
                    int cy0 = min(max(y0,   0), H-1);
                    int cy1 = min(max(y0+1, 0), H-1);
                    wt.x = wy0*wx0*mask*vy0*vx0;
                    wt.y = wy0*wx1*mask*vy0*vx1;
                    wt.z = wy1*wx0*mask*vy1*vx0;
                    wt.w = wy1*wx1*mask*vy1*vx1;
                    ix.x = (rb + cy0*W + cx0) << 5;   // float2 index
                    ix.y = (rb + cy0*W + cx1) << 5;
                    ix.z = (rb + cy1*W + cx0) << 5;
                    ix.w = (rb + cy1*W + cx1) << 5;
                }

                float2 c[4][4];
#define PI(bi, i) { \
    int q0 = __shfl_sync(0xffffffffu, ix.x, (i)); \
    int q1 = __shfl_sync(0xffffffffu, ix.y, (i)); \
    int q2 = __shfl_sync(0xffffffffu, ix.z, (i)); \
    int q3 = __shfl_sync(0xffffffffu, ix.w, (i)); \
    c[bi][0] = xp2[q0 + lane]; \
    c[bi][1] = xp2[q1 + lane]; \
    c[bi][2] = xp2[q2 + lane]; \
    c[bi][3] = xp2[q3 + lane]; }
#define PC(bi, i) { \
    float ax = __shfl_sync(0xffffffffu, wt.x, (i)); \
    float ay = __shfl_sync(0xffffffffu, wt.y, (i)); \
    float az = __shfl_sync(0xffffffffu, wt.z, (i)); \
    float aw = __shfl_sync(0xffffffffu, wt.w, (i)); \
    u64 r = fmul2(pk(ax, ax), pk(c[bi][0].x, c[bi][0].y)); \
    r = ffma2(pk(ay, ay), pk(c[bi][1].x, c[bi][1].y), r); \
    r = ffma2(pk(az, az), pk(c[bi][2].x, c[bi][2].y), r); \
    r = ffma2(pk(aw, aw), pk(c[bi][3].x, c[bi][3].y), r); \
    float2 v = upk(r); \
    unsigned h2 = bf16x2_of(v.x, v.y); \
    float hx = __uint_as_float(h2 << 16); \
    float hy = __uint_as_float(h2 & 0xffff0000u); \
    unsigned l2 = bf16x2_of(v.x - hx, v.y - hy); \
    int pxt = warp + 12*(i); \
    if (pxt < 128) { \
        unsigned boff = (unsigned)(pxt*128 + lane*4); \
        boff ^= (unsigned)((pxt & 7) << 4); \
        *(unsigned*)(aBufH + boff) = h2; \
        *(unsigned*)(aBufL + boff) = l2; \
    } }

                // issue 3 px of gathers BEFORE waiting (LDGs don't touch smem)
                PI(0, 0); PI(1, 1); PI(2, 2);
                MBAR_WAIT(sb + SMQ + stage*16 + 8, (unsigned)ph);   // empty[stage]
                char* aBufH = sm + SMA + stage*32768;
                char* aBufL = aBufH + 16384;
#pragma unroll
                for (int i = 0; i < 11; i++) {
                    if (i + 3 < 11) PI((i + 3) & 3, i + 3);
                    PC(i & 3, i);
                }
#undef PI
#undef PC
                MBAR_ARRIVE(sb + SMQ + stage*16);    // full[stage]
                if (++stage == 2) { stage = 0; ph ^= 1; }
            }
        }
    } else {
        // ================= CONSUMER (4 warps; warp q owns 32 px x 64 o) =====
        int ph = 0;
        const int q = warp - 12;                        // px quadrant
        const unsigned a_row0 = (unsigned)((q*32 + (lane & 15))*128 + (lane >> 4)*16);
        const unsigned a_row1 = a_row0 + 16*128;
        const unsigned a_swz  = (unsigned)((lane & 7) << 4);
        unsigned b_inner = (unsigned)((lane & 15)*32 + (lane >> 4)*16);
        b_inner ^= ((b_inner >> 7) & 1) << 4;

        // B streaming: 2-slot ring; 128 consumer threads copy 128B each
        const int ci = q*32 + lane;                     // 0..127
        int bs = 0;
        {
            unsigned dst = sb + SMBR + (unsigned)ci*128;
            const char* src = (const char*)g_wB + ci*128;
#pragma unroll
            for (int j = 0; j < 8; j++) CP_ASYNC16(dst + j*16, src + j*16);
            CP_COMMIT();
        }

        for (int t = blockIdx.x; t < NTILE; t += gridDim.x) {
            const int b = t >> 7;
            const int h = t & 127;

            float acc[2][8][4];
#pragma unroll
            for (int m = 0; m < 2; m++)
#pragma unroll
                for (int f = 0; f < 8; f++)
#pragma unroll
                    for (int j = 0; j < 4; j++) acc[m][f][j] = 0.f;

#pragma unroll 1
            for (int k = 0; k < 9; k++) {
                MBAR_WAIT(sb + SMQ + stage*16, (unsigned)ph);     // full[stage]
                CP_WAIT0();                                        // B_k copies done
                asm volatile("bar.sync 1, 128;" ::: "memory");

                // prefetch next tap's B into other slot
                {
                    int kn = (k == 8) ? 0 : k + 1;
                    unsigned dst = sb + SMBR + (unsigned)(bs ^ 1)*16384 + (unsigned)ci*128;
                    const char* src = (const char*)g_wB + kn*16384 + ci*128;
#pragma unroll
                    for (int j = 0; j < 8; j++) CP_ASYNC16(dst + j*16, src + j*16);
                    CP_COMMIT();
                }

                const unsigned aH = sb + SMA + stage*32768;
                const unsigned aL = aH + 16384;
                const unsigned bH = sb + SMBR + (unsigned)bs*16384;
                const unsigned bL = bH + 8192;
#pragma unroll
                for (int kc = 0; kc < 4; kc++) {
                    unsigned ai0 = (a_row0 + kc*32) ^ a_swz;
                    unsigned ai1 = (a_row1 + kc*32) ^ a_swz;
                    unsigned a0h0,a0h1,a0h2,a0h3, a0l0,a0l1,a0l2,a0l3;
                    unsigned a1h0,a1h1,a1h2,a1h3, a1l0,a1l1,a1l2,a1l3;
                    ldsm_x4(a0h0,a0h1,a0h2,a0h3, aH + ai0);
                    ldsm_x4(a0l0,a0l1,a0l2,a0l3, aL + ai0);
                    ldsm_x4(a1h0,a1h1,a1h2,a1h3, aH + ai1);
                    ldsm_x4(a1l0,a1l1,a1l2,a1l3, aL + ai1);
#pragma unroll
                    for (int nb = 0; nb < 4; nb++) {
                        unsigned blk = (unsigned)(kc*4 + nb)*512 + b_inner;
                        unsigned bh0,bh1,bh2,bh3, bl0,bl1,bl2,bl3;
                        ldsm_x4t(bh0,bh1,bh2,bh3, bH + blk);
                        ldsm_x4t(bl0,bl1,bl2,bl3, bL + blk);
                        const int f = nb*2;
                        mma16816(acc[0][f+0], a0h0,a0h1,a0h2,a0h3, bh0,bh1);
                        mma16816(acc[0][f+1], a0h0,a0h1,a0h2,a0h3, bh2,bh3);
                        mma16816(acc[0][f+0], a0h0,a0h1,a0h2,a0h3, bl0,bl1);
                        mma16816(acc[0][f+1], a0h0,a0h1,a0h2,a0h3, bl2,bl3);
                        mma16816(acc[0][f+0], a0l0,a0l1,a0l2,a0l3, bh0,bh1);
                        mma16816(acc[0][f+1], a0l0,a0l1,a0l2,a0l3, bh2,bh3);
                        mma16816(acc[1][f+0], a1h0,a1h1,a1h2,a1h3, bh0,bh1);
                        mma16816(acc[1][f+1], a1h0,a1h1,a1h2,a1h3, bh2,bh3);
                        mma16816(acc[1][f+0], a1h0,a1h1,a1h2,a1h3, bl0,bl1);
                        mma16816(acc[1][f+1], a1h0,a1h1,a1h2,a1h3, bl2,bl3);
                        mma16816(acc[1][f+0], a1l0,a1l1,a1l2,a1l3, bh0,bh1);
                        mma16816(acc[1][f+1], a1l0,a1l1,a1l2,a1l3, bh2,bh3);
                    }
                }
                MBAR_ARRIVE(sb + SMQ + stage*16 + 8);   // empty[stage]
                if (++stage == 2) { stage = 0; ph ^= 1; }
                bs ^= 1;
            }

            // epilogue: registers -> out directly in NCHW
#pragma unroll
            for (int m = 0; m < 2; m++) {
                const int px = q*32 + m*16 + (lane >> 2);
#pragma unroll
                for (int f = 0; f < 8; f++) {
                    const int o = f*8 + 2*(lane & 3);
                    float* p0 = out + ((size_t)(b*64 + o))*HW + h*W + px;
                    p0[0]      = acc[m][f][0];
                    p0[HW]     = acc[m][f][1];
                    p0[8]      = acc[m][f][2];
                    p0[HW + 8] = acc[m][f][3];
                }
            }
        }
    }
}

// ---------------- launch ----------------
extern "C" void kernel_launch(void* const* d_in, const int* in_sizes, int n_in,
                              void* d_out, int out_size) {
    const float* x      = (const float*)d_in[0];
    const float* w_off  = (const float*)d_in[1];
    const float* b_off  = (const float*)d_in[2];
    const float* w_conv = (const float*)d_in[3];
    float* out = (float*)d_out;

    const int smem_off = KIDX*28*(int)sizeof(float);   // 64512

    cudaFuncSetAttribute(k_offconv,  cudaFuncAttributeMaxDynamicSharedMemorySize, smem_off);
    cudaFuncSetAttribute(k_fused_ws, cudaFuncAttributeMaxDynamicSharedMemorySize, SMTOT);

    dim3 tgrid(HW/32, C/32, BB);
    dim3 tblk(32, 8);
    k_transpose_in<<<tgrid, tblk>>>(x);
    k_wprep<<<(9*2*64*64 + 255)/256, 256>>>(w_conv);
    k_offconv<<<NPIX/512, 256, smem_off>>>(x, w_off, b_off);
    k_fused_ws<<<152, 512, SMTOT>>>(out);
}

// round 12
// speedup vs baseline: 1.0233x; 1.0233x over previous
#include <cuda_runtime.h>
#include <cuda_bf16.h>
#include <math.h>

#define BB 8
#define C 64
#define H 128
#define W 128
#define HW (H*W)            // 16384
#define NPIX (BB*HW)        // 131072
#define CO_OFF 27
#define KIDX 576
#define NTILE 1024          // 128 px per tile (one image row)

typedef unsigned long long u64;

// ---------------- packed fp32x2 helpers ----------------
__device__ __forceinline__ u64 pk(float x, float y) {
    u64 r; asm("mov.b64 %0, {%1, %2};" : "=l"(r) : "f"(x), "f"(y)); return r;
}
__device__ __forceinline__ float2 upk(u64 a) {
    float2 f; asm("mov.b64 {%0, %1}, %2;" : "=f"(f.x), "=f"(f.y) : "l"(a)); return f;
}
__device__ __forceinline__ u64 ffma2(u64 a, u64 b, u64 c) {
    u64 d; asm("fma.rn.f32x2 %0, %1, %2, %3;" : "=l"(d) : "l"(a), "l"(b), "l"(c)); return d;
}
__device__ __forceinline__ u64 fmul2(u64 a, u64 b) {
    u64 d; asm("mul.rn.f32x2 %0, %1, %2;" : "=l"(d) : "l"(a), "l"(b)); return d;
}
// bf16x2 pack: x -> low half, y -> high half
__device__ __forceinline__ unsigned bf16x2_of(float x, float y) {
    unsigned r; asm("cvt.rn.satfinite.bf16x2.f32 %0, %1, %2;" : "=r"(r) : "f"(y), "f"(x)); return r;
}

// ---------------- mma.sync / ldmatrix (baseline PTX) ----------------
__device__ __forceinline__ void ldsm_x4(unsigned& r0, unsigned& r1, unsigned& r2, unsigned& r3,
                                        unsigned addr) {
    asm volatile("ldmatrix.sync.aligned.m8n8.x4.shared.b16 {%0,%1,%2,%3}, [%4];"
        : "=r"(r0), "=r"(r1), "=r"(r2), "=r"(r3) : "r"(addr));
}
__device__ __forceinline__ void ldsm_x4t(unsigned& r0, unsigned& r1, unsigned& r2, unsigned& r3,
                                         unsigned addr) {
    asm volatile("ldmatrix.sync.aligned.m8n8.x4.trans.shared.b16 {%0,%1,%2,%3}, [%4];"
        : "=r"(r0), "=r"(r1), "=r"(r2), "=r"(r3) : "r"(addr));
}
__device__ __forceinline__ void mma16816(float* c,
                                         unsigned a0, unsigned a1, unsigned a2, unsigned a3,
                                         unsigned b0, unsigned b1) {
    asm volatile(
        "mma.sync.aligned.m16n8k16.row.col.f32.bf16.bf16.f32 "
        "{%0,%1,%2,%3}, {%4,%5,%6,%7}, {%8,%9}, {%0,%1,%2,%3};"
        : "+f"(c[0]), "+f"(c[1]), "+f"(c[2]), "+f"(c[3])
        : "r"(a0), "r"(a1), "r"(a2), "r"(a3), "r"(b0), "r"(b1));
}
__device__ __forceinline__ unsigned smem_u32(const void* p) {
    unsigned a; asm("{ .reg .u64 t; cvta.to.shared.u64 t, %1; cvt.u32.u64 %0, t; }" : "=r"(a) : "l"(p));
    return a;
}
#define MBAR_INIT(mb, n) asm volatile("mbarrier.init.shared.b64 [%0], %1;" :: "r"(mb), "r"(n) : "memory")
#define MBAR_ARRIVE(mb)  asm volatile("mbarrier.arrive.shared.b64 _, [%0];" :: "r"(mb) : "memory")
#define MBAR_WAIT(mb, ph) do { \
    unsigned _mb = (mb), _ph = (ph), _done; \
    asm volatile("{ .reg .pred p; mbarrier.try_wait.parity.acquire.cta.shared::cta.b64 p, [%1], %2; selp.b32 %0, 1, 0, p; }" \
        : "=r"(_done) : "r"(_mb), "r"(_ph) : "memory"); \
    if (!_done) { \
        asm volatile("{ .reg .pred P1; WL_%=: mbarrier.try_wait.parity.acquire.cta.shared::cta.b64 P1, [%0], %1, 0x989680; @P1 bra.uni WD_%=; bra.uni WL_%=; WD_%=: }" \
            :: "r"(_mb), "r"(_ph) : "memory"); \
    } } while (0)
#define CP_ASYNC16(dst, src) \
    asm volatile("cp.async.ca.shared.global [%0], [%1], 16;" :: "r"(dst), "l"(src) : "memory")
#define CP_COMMIT()  asm volatile("cp.async.commit_group;" ::: "memory")
#define CP_WAIT0()   asm volatile("cp.async.wait_group 0;" ::: "memory")

// ---------------- scratch ----------------
__device__ float g_xT[NPIX*C];                            // x NHWC
__device__ float g_off[BB*CO_OFF*HW];                     // offset conv out
__device__ __align__(16) unsigned short g_wB[9*2*64*64];  // W hi/lo, ldmatrix-ready blocks

// ---------------- NCHW -> NHWC transpose of x ----------------
__global__ void k_transpose_in(const float* __restrict__ x) {
    __shared__ float tile[32][33];
    int b  = blockIdx.z;
    int c0 = blockIdx.y * 32;
    int p0 = blockIdx.x * 32;
    int tx = threadIdx.x, ty = threadIdx.y;
#pragma unroll
    for (int i = 0; i < 4; i++)
        tile[ty + 8*i][tx] = x[(b*C + c0 + ty + 8*i)*HW + p0 + tx];
    __syncthreads();
#pragma unroll
    for (int i = 0; i < 4; i++)
        g_xT[(b*HW + p0 + ty + 8*i)*C + c0 + tx] = tile[tx][ty + 8*i];
}

// ---------------- prep: W -> bf16 hi/lo ldmatrix blocks ----------------
__global__ void k_wprep(const float* __restrict__ w_conv) {
    int i = blockIdx.x * blockDim.x + threadIdx.x;
    if (i >= 9*2*64*64) return;
    int o  = i & 63;
    int ch = (i >> 6) & 63;
    int hl = (i >> 12) & 1;
    int k  = i >> 13;
    float w = w_conv[o*KIDX + ch*9 + k];
    __nv_bfloat16 hi = __float2bfloat16(w);
    unsigned short val;
    if (hl == 0) {
        val = *(unsigned short*)&hi;
    } else {
        float fhi = __bfloat162float(hi);
        __nv_bfloat16 lo = __float2bfloat16(w - fhi);
        val = *(unsigned short*)&lo;
    }
    unsigned block = (unsigned)(((k*2 + hl)*16) + (ch >> 4)*4 + (o >> 4));
    unsigned inner = (unsigned)((ch & 15)*32 + (o & 15)*2);
    inner ^= ((inner >> 7) & 1) << 4;
    *(unsigned short*)((char*)g_wB + block*512 + inner) = val;
}

// ---------------- offset-predictor 3x3 conv, pad 1, 2 px/thread ----------------
__global__ __launch_bounds__(256) void k_offconv(
    const float* __restrict__ x, const float* __restrict__ w_off,
    const float* __restrict__ b_off)
{
    extern __shared__ float sw[];   // [576][28]
    for (int i = threadIdx.x; i < CO_OFF*KIDX; i += blockDim.x) {
        int co = i / KIDX;
        int r  = i - co*KIDX;
        sw[r*28 + co] = w_off[i];
    }
    __syncthreads();

    int pix0 = blockIdx.x * 512 + threadIdx.x;
    int b  = pix0 >> 14;
    int h0 = (pix0 >> 7) & 127;
    int w0 = pix0 & 127;
    int h1 = h0 + 2;

    int   off[9];
    float vm0[9], vm1[9];
#pragma unroll
    for (int t = 0; t < 9; t++) {
        int dy = t/3 - 1, dx = t%3 - 1;
        off[t] = dy*W + dx;
        int xx = w0 + dx;
        bool vx = (xx >= 0) && (xx < W);
        int y0 = h0 + dy, y1 = h1 + dy;
        vm0[t] = (vx && y0 >= 0 && y0 < H) ? 1.f : 0.f;
        vm1[t] = (vx && y1 >= 0 && y1 < H) ? 1.f : 0.f;
    }

    u64 acc0[14], acc1[14];
#pragma unroll
    for (int j = 0; j < 13; j++) { acc0[j] = pk(b_off[2*j], b_off[2*j+1]); acc1[j] = acc0[j]; }
    acc0[13] = pk(b_off[26], 0.f); acc1[13] = acc0[13];

    const float* xc0 = x + (size_t)b*C*HW + h0*W + w0;
    const float* xc1 = xc0 + 2*W;
#pragma unroll 1
    for (int c = 0; c < C; c++) {
        float xv0[9], xv1[9];
#pragma unroll
        for (int t = 0; t < 9; t++) {
            xv0[t] = vm0[t] * __ldg(xc0 + off[t]);
            xv1[t] = vm1[t] * __ldg(xc1 + off[t]);
        }
        const float* wp = sw + c*9*28;
#pragma unroll
        for (int t = 0; t < 9; t++) {
            u64 s0 = pk(xv0[t], xv0[t]);
            u64 s1 = pk(xv1[t], xv1[t]);
#pragma unroll
            for (int j = 0; j < 7; j++) {
                float4 w4 = *(const float4*)(wp + t*28 + 4*j);
                u64 wA = pk(w4.x, w4.y);
                u64 wB = pk(w4.z, w4.w);
                acc0[2*j]   = ffma2(s0, wA, acc0[2*j]);
                acc0[2*j+1] = ffma2(s0, wB, acc0[2*j+1]);
                acc1[2*j]   = ffma2(s1, wA, acc1[2*j]);
                acc1[2*j+1] = ffma2(s1, wB, acc1[2*j+1]);
            }
        }
        xc0 += HW; xc1 += HW;
    }
    float* op0 = g_off + (size_t)b*CO_OFF*HW + h0*W + w0;
    float* op1 = op0 + 2*W;
#pragma unroll
    for (int j = 0; j < 13; j++) {
        float2 a = upk(acc0[j]); float2 bq = upk(acc1[j]);
        op0[(2*j)*HW] = a.x;  op0[(2*j+1)*HW] = a.y;
        op1[(2*j)*HW] = bq.x; op1[(2*j+1)*HW] = bq.y;
    }
    op0[26*HW] = upk(acc0[13]).x;
    op1[26*HW] = upk(acc1[13]).x;
}

// ---------------- fused: 8 producer / 8 consumer warps ----------------
// smem:
//   [0..65536)       A ring, 2 stages x (hi 16KB + lo 16KB)
//   [65536..98304)   B ring, 2 slots x 16KB, cp.async-streamed
//   [98304..102400)  params: 8 producer warps x 16 px x 32B (wt float4 + ix int4)
//   [102400..102432) mbarriers
#define SMA   0
#define SMBR  65536
#define SMP   98304
#define SMQ   102400
#define SMTOT 102464

__global__ __launch_bounds__(512, 1) void k_fused_ws(float* __restrict__ out) {
    extern __shared__ char sm[];
    const unsigned sb = smem_u32(sm);
    const int tid  = threadIdx.x;
    const int lane = tid & 31;
    const int warp = tid >> 5;

    if (tid == 0) {
        MBAR_INIT(sb + SMQ + 0,  256);   // full0  (producer threads arrive)
        MBAR_INIT(sb + SMQ + 8,  256);   // empty0 (consumer threads arrive)
        MBAR_INIT(sb + SMQ + 16, 256);   // full1
        MBAR_INIT(sb + SMQ + 24, 256);   // empty1
    }
    __syncthreads();

    int stage = 0;

    if (warp < 8) {
        // ================= PRODUCER (warp owns px warp*16..warp*16+15) =====
        int ph = 1;
        const float2* xp2 = (const float2*)g_xT;
        const int wx = warp*16 + lane;                  // lane<16 param px
        const unsigned parw = sb + SMP + (unsigned)warp*512;
        const char* parp = sm + SMP + warp*512;

        for (int t = blockIdx.x; t < NTILE; t += gridDim.x) {
            const int b  = t >> 7;
            const int h  = t & 127;
            const int rb = b * HW;
            const int obase0 = b*CO_OFF*HW + h*W + wx;

            float no1 = 0.f, no2 = 0.f, nmv = 0.f;
            if (lane < 16) {
                no1 = __ldg(g_off + obase0);
                no2 = __ldg(g_off + obase0 +  9*HW);
                nmv = __ldg(g_off + obase0 + 18*HW);
            }

#pragma unroll 1
            for (int k = 0; k < 9; k++) {
                float o1 = no1, o2 = no2, mv = nmv;
                if (k < 8 && lane < 16) {
                    int ob = obase0 + (k+1)*HW;
                    no1 = __ldg(g_off + ob);
                    no2 = __ldg(g_off + ob +  9*HW);
                    nmv = __ldg(g_off + ob + 18*HW);
                }

                // per-lane params for px = wx, staged to warp-private smem
                {
                    float mask = 1.f / (1.f + expf(-mv));
                    int kh = k / 3;
                    int kw = k - kh*3;
                    float px = o1 + (float)(wx + kw - 1);
                    float py = o2 + (float)(h + kh - 1);
                    float x0f = floorf(px), y0f = floorf(py);
                    int x0 = (int)x0f, y0 = (int)y0f;
                    float wx1 = px - x0f, wy1 = py - y0f;
                    float wx0 = 1.f - wx1, wy0 = 1.f - wy1;
                    float vx0 = (x0 >= 0  && x0     < W) ? 1.f : 0.f;
                    float vx1 = (x0 >= -1 && x0 + 1 < W) ? 1.f : 0.f;
                    float vy0 = (y0 >= 0  && y0     < H) ? 1.f : 0.f;
                    float vy1 = (y0 >= -1 && y0 + 1 < H) ? 1.f : 0.f;
                    int cx0 = min(max(x0,   0), W-1);
                    int cx1 = min(max(x0+1, 0), W-1);
                    int cy0 = min(max(y0,   0), H-1);
                    int cy1 = min(max(y0+1, 0), H-1);
                    float4 wt;
                    wt.x = wy0*wx0*mask*vy0*vx0;
                    wt.y = wy0*wx1*mask*vy0*vx1;
                    wt.z = wy1*wx0*mask*vy1*vx0;
                    wt.w = wy1*wx1*mask*vy1*vx1;
                    int4 ix;
                    ix.x = (rb + cy0*W + cx0) << 5;   // float2 index
                    ix.y = (rb + cy0*W + cx1) << 5;
                    ix.z = (rb + cy1*W + cx0) << 5;
                    ix.w = (rb + cy1*W + cx1) << 5;
                    if (lane < 16) {
                        *(float4*)(parp + lane*32)      = wt;
                        *(int4*)  (parp + lane*32 + 16) = ix;
                    }
                }
                __syncwarp();

                // pipelined gathers: 4-px batches, 2-batch lookahead
                float2 c[3][16];
#define P_ISSUE(bi, p4) { \
    _Pragma("unroll") \
    for (int j = 0; j < 4; j++) { \
        int pp = (p4)*4 + j; \
        int4 qi = *(const int4*)(parp + pp*32 + 16);   /* broadcast LDS.128 */ \
        c[bi][j*4+0] = xp2[qi.x + lane]; \
        c[bi][j*4+1] = xp2[qi.y + lane]; \
        c[bi][j*4+2] = xp2[qi.z + lane]; \
        c[bi][j*4+3] = xp2[qi.w + lane]; \
    } }
#define P_COMBINE(bi, p4) { \
    _Pragma("unroll") \
    for (int j = 0; j < 4; j++) { \
        int pp = (p4)*4 + j; \
        float4 wt4 = *(const float4*)(parp + pp*32);   /* broadcast LDS.128 */ \
        u64 r = fmul2(pk(wt4.x, wt4.x), pk(c[bi][j*4+0].x, c[bi][j*4+0].y)); \
        r = ffma2(pk(wt4.y, wt4.y), pk(c[bi][j*4+1].x, c[bi][j*4+1].y), r); \
        r = ffma2(pk(wt4.z, wt4.z), pk(c[bi][j*4+2].x, c[bi][j*4+2].y), r); \
        r = ffma2(pk(wt4.w, wt4.w), pk(c[bi][j*4+3].x, c[bi][j*4+3].y), r); \
        float2 v = upk(r); \
        unsigned h2 = bf16x2_of(v.x, v.y); \
        float hx = __uint_as_float(h2 << 16); \
        float hy = __uint_as_float(h2 & 0xffff0000u); \
        unsigned l2 = bf16x2_of(v.x - hx, v.y - hy); \
        int pxt = warp*16 + pp; \
        unsigned boff = (unsigned)(pxt*128 + lane*4); \
        boff ^= (unsigned)((pxt & 7) << 4); \
        *(unsigned*)(aBufH + boff) = h2; \
        *(unsigned*)(aBufL + boff) = l2; \
    } }

                // issue first two batches BEFORE waiting (LDG/LDS-param only)
                P_ISSUE(0, 0);
                P_ISSUE(1, 1);
                MBAR_WAIT(sb + SMQ + stage*16 + 8, (unsigned)ph);   // empty[stage]
                char* aBufH = sm + SMA + stage*32768;
                char* aBufL = aBufH + 16384;
                P_ISSUE(2, 2);
                P_COMBINE(0, 0);
                P_ISSUE(0, 3);
                P_COMBINE(1, 1);
                P_COMBINE(2, 2);
                P_COMBINE(0, 3);
#undef P_ISSUE
#undef P_COMBINE
                MBAR_ARRIVE(sb + SMQ + stage*16);    // full[stage]
                if (++stage == 2) { stage = 0; ph ^= 1; }
            }
        }
    } else {
        // ================= CONSUMER (8 warps: 32px x 32o tiles) =============
        int ph = 0;
        const int cw  = warp - 8;
        const int pxc = cw & 3;          // 32-px chunk
        const int oh  = cw >> 2;         // 32-o half
        const unsigned a_row0 = (unsigned)((pxc*32 + (lane & 15))*128 + (lane >> 4)*16);
        const unsigned a_row1 = a_row0 + 16*128;
        const unsigned a_swz  = (unsigned)((lane & 7) << 4);
        unsigned b_inner = (unsigned)((lane & 15)*32 + (lane >> 4)*16);
        b_inner ^= ((b_inner >> 7) & 1) << 4;

        // B streaming: 2-slot ring, each thread copies its 64B of the 16KB slot
        const int ci = cw*32 + lane;                 // 0..255
        int bs = 0;
        {
            unsigned dst = sb + SMBR + (unsigned)ci*64;
            const char* src = (const char*)g_wB + ci*64;
#pragma unroll
            for (int j = 0; j < 4; j++) CP_ASYNC16(dst + j*16, src + j*16);
            CP_COMMIT();
        }

        for (int t = blockIdx.x; t < NTILE; t += gridDim.x) {
            const int b = t >> 7;
            const int h = t & 127;

            float acc[2][4][4];
#pragma unroll
            for (int m = 0; m < 2; m++)
#pragma unroll
                for (int f = 0; f < 4; f++)
#pragma unroll
                    for (int j = 0; j < 4; j++) acc[m][f][j] = 0.f;

#pragma unroll 1
            for (int k = 0; k < 9; k++) {
                MBAR_WAIT(sb + SMQ + stage*16, (unsigned)ph);     // full[stage]
                CP_WAIT0();                                        // B_k copies done
                asm volatile("bar.sync 1, 256;" ::: "memory");

                // prefetch next tap's B into other slot
                {
                    int kn = (k == 8) ? 0 : k + 1;
                    unsigned dst = sb + SMBR + (unsigned)(bs ^ 1)*16384 + (unsigned)ci*64;
                    const char* src = (const char*)g_wB + kn*16384 + ci*64;
#pragma unroll
                    for (int j = 0; j < 4; j++) CP_ASYNC16(dst + j*16, src + j*16);
                    CP_COMMIT();
                }

                const unsigned aH = sb + SMA + stage*32768;
                const unsigned aL = aH + 16384;
                const unsigned bH = sb + SMBR + (unsigned)bs*16384;
                const unsigned bL = bH + 8192;
#pragma unroll
                for (int kc = 0; kc < 4; kc++) {
                    unsigned ai0 = (a_row0 + kc*32) ^ a_swz;
                    unsigned ai1 = (a_row1 + kc*32) ^ a_swz;
                    unsigned a0h0,a0h1,a0h2,a0h3, a0l0,a0l1,a0l2,a0l3;
                    unsigned a1h0,a1h1,a1h2,a1h3, a1l0,a1l1,a1l2,a1l3;
                    ldsm_x4(a0h0,a0h1,a0h2,a0h3, aH + ai0);
                    ldsm_x4(a0l0,a0l1,a0l2,a0l3, aL + ai0);
                    ldsm_x4(a1h0,a1h1,a1h2,a1h3, aH + ai1);
                    ldsm_x4(a1l0,a1l1,a1l2,a1l3, aL + ai1);
#pragma unroll
                    for (int nb = 0; nb < 2; nb++) {
                        unsigned blk = (unsigned)(kc*4 + oh*2 + nb)*512 + b_inner;
                        unsigned bh0,bh1,bh2,bh3, bl0,bl1,bl2,bl3;
                        ldsm_x4t(bh0,bh1,bh2,bh3, bH + blk);
                        ldsm_x4t(bl0,bl1,bl2,bl3, bL + blk);
                        mma16816(acc[0][nb*2+0], a0h0,a0h1,a0h2,a0h3, bh0,bh1);
                        mma16816(acc[0][nb*2+1], a0h0,a0h1,a0h2,a0h3, bh2,bh3);
                        mma16816(acc[0][nb*2+0], a0h0,a0h1,a0h2,a0h3, bl0,bl1);
                        mma16816(acc[0][nb*2+1], a0h0,a0h1,a0h2,a0h3, bl2,bl3);
                        mma16816(acc[0][nb*2+0], a0l0,a0l1,a0l2,a0l3, bh0,bh1);
                        mma16816(acc[0][nb*2+1], a0l0,a0l1,a0l2,a0l3, bh2,bh3);
                        mma16816(acc[1][nb*2+0], a1h0,a1h1,a1h2,a1h3, bh0,bh1);
                        mma16816(acc[1][nb*2+1], a1h0,a1h1,a1h2,a1h3, bh2,bh3);
                        mma16816(acc[1][nb*2+0], a1h0,a1h1,a1h2,a1h3, bl0,bl1);
                        mma16816(acc[1][nb*2+1], a1h0,a1h1,a1h2,a1h3, bl2,bl3);
                        mma16816(acc[1][nb*2+0], a1l0,a1l1,a1l2,a1l3, bh0,bh1);
                        mma16816(acc[1][nb*2+1], a1l0,a1l1,a1l2,a1l3, bh2,bh3);
                    }
                }
                MBAR_ARRIVE(sb + SMQ + stage*16 + 8);   // empty[stage]
                if (++stage == 2) { stage = 0; ph ^= 1; }
                bs ^= 1;
            }

            // epilogue: registers -> out directly in NCHW
            const int oc0 = oh*32 + 2*(lane & 3);
#pragma unroll
            for (int m = 0; m < 2; m++) {
                const int px = pxc*32 + m*16 + (lane >> 2);
#pragma unroll
                for (int f = 0; f < 4; f++) {
                    const int oc = oc0 + (f >> 1)*16 + (f & 1)*8;
                    float* p0 = out + ((size_t)(b*64 + oc))*HW + h*W + px;
                    p0[0]      = acc[m][f][0];
                    p0[HW]     = acc[m][f][1];
                    p0[8]      = acc[m][f][2];
                    p0[HW + 8] = acc[m][f][3];
                }
            }
        }
    }
}

// ---------------- launch ----------------
extern "C" void kernel_launch(void* const* d_in, const int* in_sizes, int n_in,
                              void* d_out, int out_size) {
    const float* x      = (const float*)d_in[0];
    const float* w_off  = (const float*)d_in[1];
    const float* b_off  = (const float*)d_in[2];
    const float* w_conv = (const float*)d_in[3];
    float* out = (float*)d_out;

    const int smem_off = KIDX*28*(int)sizeof(float);   // 64512

    cudaFuncSetAttribute(k_offconv,  cudaFuncAttributeMaxDynamicSharedMemorySize, smem_off);
    cudaFuncSetAttribute(k_fused_ws, cudaFuncAttributeMaxDynamicSharedMemorySize, SMTOT);

    dim3 tgrid(HW/32, C/32, BB);
    dim3 tblk(32, 8);
    k_transpose_in<<<tgrid, tblk>>>(x);
    k_wprep<<<(9*2*64*64 + 255)/256, 256>>>(w_conv);
    k_offconv<<<NPIX/512, 256, smem_off>>>(x, w_off, b_off);
    k_fused_ws<<<152, 512, SMTOT>>>(out);
}

// round 14
// speedup vs baseline: 1.0775x; 1.0529x over previous
#include <cuda_runtime.h>
#include <cuda_bf16.h>
#include <math.h>

#define BB 8
#define C 64
#define H 128
#define W 128
#define HW (H*W)            // 16384
#define NPIX (BB*HW)        // 131072
#define CO_OFF 27
#define KIDX 576
#define NTILE 1024          // 128 px per tile (one image row)

typedef unsigned long long u64;

// ---------------- packed fp32x2 helpers ----------------
__device__ __forceinline__ u64 pk(float x, float y) {
    u64 r; asm("mov.b64 %0, {%1, %2};" : "=l"(r) : "f"(x), "f"(y)); return r;
}
__device__ __forceinline__ float2 upk(u64 a) {
    float2 f; asm("mov.b64 {%0, %1}, %2;" : "=f"(f.x), "=f"(f.y) : "l"(a)); return f;
}
__device__ __forceinline__ u64 ffma2(u64 a, u64 b, u64 c) {
    u64 d; asm("fma.rn.f32x2 %0, %1, %2, %3;" : "=l"(d) : "l"(a), "l"(b), "l"(c)); return d;
}
__device__ __forceinline__ u64 fmul2(u64 a, u64 b) {
    u64 d; asm("mul.rn.f32x2 %0, %1, %2;" : "=l"(d) : "l"(a), "l"(b)); return d;
}
// bf16x2 pack: x -> low half, y -> high half
__device__ __forceinline__ unsigned bf16x2_of(float x, float y) {
    unsigned r; asm("cvt.rn.satfinite.bf16x2.f32 %0, %1, %2;" : "=r"(r) : "f"(y), "f"(x)); return r;
}

// ---------------- mma.sync / ldmatrix (baseline PTX) ----------------
__device__ __forceinline__ void ldsm_x4(unsigned& r0, unsigned& r1, unsigned& r2, unsigned& r3,
                                        unsigned addr) {
    asm volatile("ldmatrix.sync.aligned.m8n8.x4.shared.b16 {%0,%1,%2,%3}, [%4];"
        : "=r"(r0), "=r"(r1), "=r"(r2), "=r"(r3) : "r"(addr));
}
__device__ __forceinline__ void ldsm_x4t(unsigned& r0, unsigned& r1, unsigned& r2, unsigned& r3,
                                         unsigned addr) {
    asm volatile("ldmatrix.sync.aligned.m8n8.x4.trans.shared.b16 {%0,%1,%2,%3}, [%4];"
        : "=r"(r0), "=r"(r1), "=r"(r2), "=r"(r3) : "r"(addr));
}
__device__ __forceinline__ void mma16816(float* c,
                                         unsigned a0, unsigned a1, unsigned a2, unsigned a3,
                                         unsigned b0, unsigned b1) {
    asm volatile(
        "mma.sync.aligned.m16n8k16.row.col.f32.bf16.bf16.f32 "
        "{%0,%1,%2,%3}, {%4,%5,%6,%7}, {%8,%9}, {%0,%1,%2,%3};"
        : "+f"(c[0]), "+f"(c[1]), "+f"(c[2]), "+f"(c[3])
        : "r"(a0), "r"(a1), "r"(a2), "r"(a3), "r"(b0), "r"(b1));
}
__device__ __forceinline__ unsigned smem_u32(const void* p) {
    unsigned a; asm("{ .reg .u64 t; cvta.to.shared.u64 t, %1; cvt.u32.u64 %0, t; }" : "=r"(a) : "l"(p));
    return a;
}
#define MBAR_INIT(mb, n) asm volatile("mbarrier.init.shared.b64 [%0], %1;" :: "r"(mb), "r"(n) : "memory")
#define MBAR_ARRIVE(mb)  asm volatile("mbarrier.arrive.shared.b64 _, [%0];" :: "r"(mb) : "memory")
#define MBAR_WAIT(mb, ph) do { \
    unsigned _mb = (mb), _ph = (ph), _done; \
    asm volatile("{ .reg .pred p; mbarrier.try_wait.parity.acquire.cta.shared::cta.b64 p, [%1], %2; selp.b32 %0, 1, 0, p; }" \
        : "=r"(_done) : "r"(_mb), "r"(_ph) : "memory"); \
    if (!_done) { \
        asm volatile("{ .reg .pred P1; WL_%=: mbarrier.try_wait.parity.acquire.cta.shared::cta.b64 P1, [%0], %1, 0x989680; @P1 bra.uni WD_%=; bra.uni WL_%=; WD_%=: }" \
            :: "r"(_mb), "r"(_ph) : "memory"); \
    } } while (0)
#define CP_ASYNC16(dst, src) \
    asm volatile("cp.async.ca.shared.global [%0], [%1], 16;" :: "r"(dst), "l"(src) : "memory")
#define CP_COMMIT()  asm volatile("cp.async.commit_group;" ::: "memory")
#define CP_WAIT0()   asm volatile("cp.async.wait_group 0;" ::: "memory")

// ---------------- scratch ----------------
__device__ float g_xT[NPIX*C];                            // x NHWC
__device__ float g_off[BB*CO_OFF*HW];                     // offset conv out
__device__ __align__(16) unsigned short g_wB[9*2*64*64];  // w_conv hi/lo ldmatrix blocks
__device__ __align__(16) unsigned short g_wOB[9*2*64*32]; // w_off hi/lo ldmatrix blocks (N pad 32)

// ---------------- NCHW -> NHWC transpose of x ----------------
__global__ void k_transpose_in(const float* __restrict__ x) {
    __shared__ float tile[32][33];
    int b  = blockIdx.z;
    int c0 = blockIdx.y * 32;
    int p0 = blockIdx.x * 32;
    int tx = threadIdx.x, ty = threadIdx.y;
#pragma unroll
    for (int i = 0; i < 4; i++)
        tile[ty + 8*i][tx] = x[(b*C + c0 + ty + 8*i)*HW + p0 + tx];
    __syncthreads();
#pragma unroll
    for (int i = 0; i < 4; i++)
        g_xT[(b*HW + p0 + ty + 8*i)*C + c0 + tx] = tile[tx][ty + 8*i];
}

// ---------------- prep: w_conv -> bf16 hi/lo ldmatrix blocks ----------------
__global__ void k_wprep(const float* __restrict__ w_conv) {
    int i = blockIdx.x * blockDim.x + threadIdx.x;
    if (i >= 9*2*64*64) return;
    int o  = i & 63;
    int ch = (i >> 6) & 63;
    int hl = (i >> 12) & 1;
    int k  = i >> 13;
    float w = w_conv[o*KIDX + ch*9 + k];
    __nv_bfloat16 hi = __float2bfloat16(w);
    unsigned short val;
    if (hl == 0) {
        val = *(unsigned short*)&hi;
    } else {
        float fhi = __bfloat162float(hi);
        __nv_bfloat16 lo = __float2bfloat16(w - fhi);
        val = *(unsigned short*)&lo;
    }
    unsigned block = (unsigned)(((k*2 + hl)*16) + (ch >> 4)*4 + (o >> 4));
    unsigned inner = (unsigned)((ch & 15)*32 + (o & 15)*2);
    inner ^= ((inner >> 7) & 1) << 4;
    *(unsigned short*)((char*)g_wB + block*512 + inner) = val;
}

// ---------------- prep: w_off -> bf16 hi/lo ldmatrix blocks (N=32 pad) ------
__global__ void k_woffprep(const float* __restrict__ w_off) {
    int i = blockIdx.x * blockDim.x + threadIdx.x;
    if (i >= 9*2*64*32) return;
    int co = i & 31;
    int ch = (i >> 5) & 63;
    int hl = (i >> 11) & 1;
    int t  = i >> 12;
    float w = (co < CO_OFF) ? w_off[co*KIDX + ch*9 + t] : 0.f;
    __nv_bfloat16 hi = __float2bfloat16(w);
    unsigned short val;
    if (hl == 0) {
        val = *(unsigned short*)&hi;
    } else {
        float fhi = __bfloat162float(hi);
        __nv_bfloat16 lo = __float2bfloat16(w - fhi);
        val = *(unsigned short*)&lo;
    }
    unsigned block = (unsigned)((t*2 + hl)*8 + (ch >> 4)*2 + (co >> 4));
    unsigned inner = (unsigned)((ch & 15)*32 + (co & 15)*2);
    inner ^= ((inner >> 7) & 1) << 4;
    *(unsigned short*)((char*)g_wOB + block*512 + inner) = val;
}

// ---------------- offset conv via mma: off[px,27] = im2col @ w_off^T --------
// smem: [0..73728)        B blocks (9 taps x hl x [4 kc][2 n16] x 512B)
//       [73728..90112)    A hi [128px][64ch] bf16 swizzled (16384 B)
//       [90112..106496)   A lo (16384 B)
#define OB_B   0
#define OB_AH  73728
#define OB_AL  90112
#define OB_TOT 106496

__global__ __launch_bounds__(512, 1) void k_offconv_tc(const float* __restrict__ b_off) {
    extern __shared__ char sm[];
    const unsigned sb = smem_u32(sm);
    const int tid  = threadIdx.x;
    const int lane = tid & 31;
    const int warp = tid >> 5;

    // stage B once (73728 B)
    {
        const int4* src = (const int4*)g_wOB;
        int4* dst = (int4*)(sm + OB_B);
        for (int i = tid; i < 73728/16; i += 512) dst[i] = src[i];
    }
    __syncthreads();

    // A-build mapping: thread -> (px p, quarter q of 16 channels)
    const int p = tid >> 2;
    const int q = tid & 3;
    // MMA mapping: warp -> (16-px chunk, 16-o half)
    const int pxc = warp & 7;
    const int nh  = warp >> 3;
    const unsigned a_row = (unsigned)((pxc*16 + (lane & 15))*128 + (lane >> 4)*16);
    const unsigned a_swz = (unsigned)((lane & 7) << 4);
    unsigned b_inner = (unsigned)((lane & 15)*32 + (lane >> 4)*16);
    b_inner ^= ((b_inner >> 7) & 1) << 4;

    // bias for this lane's two output columns
    const int o0 = nh*16 + 2*(lane & 3);       // n8 block 0
    const int o1 = o0 + 8;                     // n8 block 1
    float bia00 = (o0 < CO_OFF)     ? __ldg(b_off + o0)     : 0.f;
    float bia01 = (o0+1 < CO_OFF)   ? __ldg(b_off + o0 + 1) : 0.f;
    float bia10 = (o1 < CO_OFF)     ? __ldg(b_off + o1)     : 0.f;
    float bia11 = (o1+1 < CO_OFF)   ? __ldg(b_off + o1 + 1) : 0.f;

    for (int t = blockIdx.x; t < NTILE; t += gridDim.x) {
        const int b = t >> 7;
        const int h = t & 127;

        float acc[2][4];
#pragma unroll
        for (int n = 0; n < 2; n++)
#pragma unroll
            for (int j = 0; j < 4; j++) acc[n][j] = 0.f;

#pragma unroll 1
        for (int k = 0; k < 9; k++) {
            // ---- build A chunk for tap k ----
            const int dy = k/3 - 1, dx = k%3 - 1;
            const int srch = h + dy;
            const int srcw = p + dx;
            const bool valid = (srch >= 0) && (srch < H) && (srcw >= 0) && (srcw < W);
            float4 f[4];
            if (valid) {
                const float4* src = (const float4*)(g_xT + ((size_t)(b*HW + srch*W + srcw))*64 + q*16);
#pragma unroll
                for (int j = 0; j < 4; j++) f[j] = src[j];
            } else {
#pragma unroll
                for (int j = 0; j < 4; j++) f[j] = make_float4(0.f, 0.f, 0.f, 0.f);
            }
            uint4 hi2[2], lo2[2];
#pragma unroll
            for (int u = 0; u < 2; u++) {
                float4 a = f[2*u], c = f[2*u+1];
                unsigned h0 = bf16x2_of(a.x, a.y);
                unsigned h1 = bf16x2_of(a.z, a.w);
                unsigned h2v = bf16x2_of(c.x, c.y);
                unsigned h3 = bf16x2_of(c.z, c.w);
                hi2[u] = make_uint4(h0, h1, h2v, h3);
                lo2[u].x = bf16x2_of(a.x - __uint_as_float(h0 << 16),
                                     a.y - __uint_as_float(h0 & 0xffff0000u));
                lo2[u].y = bf16x2_of(a.z - __uint_as_float(h1 << 16),
                                     a.w - __uint_as_float(h1 & 0xffff0000u));
                lo2[u].z = bf16x2_of(c.x - __uint_as_float(h2v << 16),
                                     c.y - __uint_as_float(h2v & 0xffff0000u));
                lo2[u].w = bf16x2_of(c.z - __uint_as_float(h3 << 16),
                                     c.w - __uint_as_float(h3 & 0xffff0000u));
            }
            {
                unsigned base = (unsigned)(p*128 + q*32);
                unsigned u0 = (base)      ^ (unsigned)((p & 7) << 4);
                unsigned u1 = (base + 16) ^ (unsigned)((p & 7) << 4);
                *(uint4*)(sm + OB_AH + u0) = hi2[0];
                *(uint4*)(sm + OB_AH + u1) = hi2[1];
                *(uint4*)(sm + OB_AL + u0) = lo2[0];
                *(uint4*)(sm + OB_AL + u1) = lo2[1];
            }
            __syncthreads();

            // ---- MMA for tap k ----
            const unsigned aH = sb + OB_AH;
            const unsigned aL = sb + OB_AL;
            const unsigned bBase = sb + OB_B + (unsigned)(k*2)*4096;     // hl=0
            const unsigned bBaseL = bBase + 4096;                        // hl=1
#pragma unroll
            for (int kc = 0; kc < 4; kc++) {
                unsigned ai = (a_row + kc*32) ^ a_swz;
                unsigned ah0, ah1, ah2, ah3, al0, al1, al2, al3;
                ldsm_x4(ah0, ah1, ah2, ah3, aH + ai);
                ldsm_x4(al0, al1, al2, al3, aL + ai);
                unsigned blk = (unsigned)(kc*2 + nh)*512 + b_inner;
                unsigned bh0, bh1, bh2, bh3, bl0, bl1, bl2, bl3;
                ldsm_x4t(bh0, bh1, bh2, bh3, bBase + blk);
                ldsm_x4t(bl0, bl1, bl2, bl3, bBaseL + blk);
                mma16816(acc[0], ah0, ah1, ah2, ah3, bh0, bh1);
                mma16816(acc[1], ah0, ah1, ah2, ah3, bh2, bh3);
                mma16816(acc[0], ah0, ah1, ah2, ah3, bl0, bl1);
                mma16816(acc[1], ah0, ah1, ah2, ah3, bl2, bl3);
                mma16816(acc[0], al0, al1, al2, al3, bh0, bh1);
                mma16816(acc[1], al0, al1, al2, al3, bh2, bh3);
            }
            __syncthreads();      // A buffer reusable for next tap
        }

        // ---- epilogue: + bias, scatter NCHW into g_off ----
        const int px0 = pxc*16 + (lane >> 2);
        float* gb = g_off + (size_t)b*CO_OFF*HW + h*W;
        if (o0 < CO_OFF) {
            gb[o0*HW + px0]         = acc[0][0] + bia00;
            gb[o0*HW + px0 + 8]     = acc[0][2] + bia00;
        }
        if (o0 + 1 < CO_OFF) {
            gb[(o0+1)*HW + px0]     = acc[0][1] + bia01;
            gb[(o0+1)*HW + px0 + 8] = acc[0][3] + bia01;
        }
        if (o1 < CO_OFF) {
            gb[o1*HW + px0]         = acc[1][0] + bia10;
            gb[o1*HW + px0 + 8]     = acc[1][2] + bia10;
        }
        if (o1 + 1 < CO_OFF) {
            gb[(o1+1)*HW + px0]     = acc[1][1] + bia11;
            gb[(o1+1)*HW + px0 + 8] = acc[1][3] + bia11;
        }
    }
}

// ---------------- fused: 8 producer / 8 consumer warps (round-12 best) -----
#define SMA   0
#define SMBR  65536
#define SMP   98304
#define SMQ   102400
#define SMTOT 102464

__global__ __launch_bounds__(512, 1) void k_fused_ws(float* __restrict__ out) {
    extern __shared__ char sm[];
    const unsigned sb = smem_u32(sm);
    const int tid  = threadIdx.x;
    const int lane = tid & 31;
    const int warp = tid >> 5;

    if (tid == 0) {
        MBAR_INIT(sb + SMQ + 0,  256);
        MBAR_INIT(sb + SMQ + 8,  256);
        MBAR_INIT(sb + SMQ + 16, 256);
        MBAR_INIT(sb + SMQ + 24, 256);
    }
    __syncthreads();

    int stage = 0;

    if (warp < 8) {
        // ================= PRODUCER =================
        int ph = 1;
        const float2* xp2 = (const float2*)g_xT;
        const int wx = warp*16 + lane;
        const char* parp = sm + SMP + warp*512;

        for (int t = blockIdx.x; t < NTILE; t += gridDim.x) {
            const int b  = t >> 7;
            const int h  = t & 127;
            const int rb = b * HW;
            const int obase0 = b*CO_OFF*HW + h*W + wx;

            float no1 = 0.f, no2 = 0.f, nmv = 0.f;
            if (lane < 16) {
                no1 = __ldg(g_off + obase0);
                no2 = __ldg(g_off + obase0 +  9*HW);
                nmv = __ldg(g_off + obase0 + 18*HW);
            }

#pragma unroll 1
            for (int k = 0; k < 9; k++) {
                float o1 = no1, o2 = no2, mv = nmv;
                if (k < 8 && lane < 16) {
                    int ob = obase0 + (k+1)*HW;
                    no1 = __ldg(g_off + ob);
                    no2 = __ldg(g_off + ob +  9*HW);
                    nmv = __ldg(g_off + ob + 18*HW);
                }

                {
                    float mask = 1.f / (1.f + expf(-mv));
                    int kh = k / 3;
                    int kw = k - kh*3;
                    float px = o1 + (float)(wx + kw - 1);
                    float py = o2 + (float)(h + kh - 1);
                    float x0f = floorf(px), y0f = floorf(py);
                    int x0 = (int)x0f, y0 = (int)y0f;
                    float wx1 = px - x0f, wy1 = py - y0f;
                    float wx0 = 1.f - wx1, wy0 = 1.f - wy1;
                    float vx0 = (x0 >= 0  && x0     < W) ? 1.f : 0.f;
                    float vx1 = (x0 >= -1 && x0 + 1 < W) ? 1.f : 0.f;
                    float vy0 = (y0 >= 0  && y0     < H) ? 1.f : 0.f;
                    float vy1 = (y0 >= -1 && y0 + 1 < H) ? 1.f : 0.f;
                    int cx0 = min(max(x0,   0), W-1);
                    int cx1 = min(max(x0+1, 0), W-1);
                    int cy0 = min(max(y0,   0), H-1);
                    int cy1 = min(max(y0+1, 0), H-1);
                    float4 wt;
                    wt.x = wy0*wx0*mask*vy0*vx0;
                    wt.y = wy0*wx1*mask*vy0*vx1;
                    wt.z = wy1*wx0*mask*vy1*vx0;
                    wt.w = wy1*wx1*mask*vy1*vx1;
                    int4 ix;
                    ix.x = (rb + cy0*W + cx0) << 5;
                    ix.y = (rb + cy0*W + cx1) << 5;
                    ix.z = (rb + cy1*W + cx0) << 5;
                    ix.w = (rb + cy1*W + cx1) << 5;
                    if (lane < 16) {
                        *(float4*)((char*)parp + lane*32)      = wt;
                        *(int4*)  ((char*)parp + lane*32 + 16) = ix;
                    }
                }
                __syncwarp();

                float2 c[3][16];
#define P_ISSUE(bi, p4) { \
    _Pragma("unroll") \
    for (int j = 0; j < 4; j++) { \
        int pp = (p4)*4 + j; \
        int4 qi = *(const int4*)(parp + pp*32 + 16); \
        c[bi][j*4+0] = xp2[qi.x + lane]; \
        c[bi][j*4+1] = xp2[qi.y + lane]; \
        c[bi][j*4+2] = xp2[qi.z + lane]; \
        c[bi][j*4+3] = xp2[qi.w + lane]; \
    } }
#define P_COMBINE(bi, p4) { \
    _Pragma("unroll") \
    for (int j = 0; j < 4; j++) { \
        int pp = (p4)*4 + j; \
        float4 wt4 = *(const float4*)(parp + pp*32); \
        u64 r = fmul2(pk(wt4.x, wt4.x), pk(c[bi][j*4+0].x, c[bi][j*4+0].y)); \
        r = ffma2(pk(wt4.y, wt4.y), pk(c[bi][j*4+1].x, c[bi][j*4+1].y), r); \
        r = ffma2(pk(wt4.z, wt4.z), pk(c[bi][j*4+2].x, c[bi][j*4+2].y), r); \
        r = ffma2(pk(wt4.w, wt4.w), pk(c[bi][j*4+3].x, c[bi][j*4+3].y), r); \
        float2 v = upk(r); \
        unsigned h2 = bf16x2_of(v.x, v.y); \
        float hx = __uint_as_float(h2 << 16); \
        float hy = __uint_as_float(h2 & 0xffff0000u); \
        unsigned l2 = bf16x2_of(v.x - hx, v.y - hy); \
        int pxt = warp*16 + pp; \
        unsigned boff = (unsigned)(pxt*128 + lane*4); \
        boff ^= (unsigned)((pxt & 7) << 4); \
        *(unsigned*)(aBufH + boff) = h2; \
        *(unsigned*)(aBufL + boff) = l2; \
    } }

                P_ISSUE(0, 0);
                P_ISSUE(1, 1);
                MBAR_WAIT(sb + SMQ + stage*16 + 8, (unsigned)ph);
                char* aBufH = sm + SMA + stage*32768;
                char* aBufL = aBufH + 16384;
                P_ISSUE(2, 2);
                P_COMBINE(0, 0);
                P_ISSUE(0, 3);
                P_COMBINE(1, 1);
                P_COMBINE(2, 2);
                P_COMBINE(0, 3);
#undef P_ISSUE
#undef P_COMBINE
                MBAR_ARRIVE(sb + SMQ + stage*16);
                if (++stage == 2) { stage = 0; ph ^= 1; }
            }
        }
    } else {
        // ================= CONSUMER =================
        int ph = 0;
        const int cw  = warp - 8;
        const int pxc = cw & 3;
        const int oh  = cw >> 2;
        const unsigned a_row0 = (unsigned)((pxc*32 + (lane & 15))*128 + (lane >> 4)*16);
        const unsigned a_row1 = a_row0 + 16*128;
        const unsigned a_swz  = (unsigned)((lane & 7) << 4);
        unsigned b_inner = (unsigned)((lane & 15)*32 + (lane >> 4)*16);
        b_inner ^= ((b_inner >> 7) & 1) << 4;

        const int ci = cw*32 + lane;
        int bs = 0;
        {
            unsigned dst = sb + SMBR + (unsigned)ci*64;
            const char* src = (const char*)g_wB + ci*64;
#pragma unroll
            for (int j = 0; j < 4; j++) CP_ASYNC16(dst + j*16, src + j*16);
            CP_COMMIT();
        }

        for (int t = blockIdx.x; t < NTILE; t += gridDim.x) {
            const int b = t >> 7;
            const int h = t & 127;

            float acc[2][4][4];
#pragma unroll
            for (int m = 0; m < 2; m++)
#pragma unroll
                for (int f = 0; f < 4; f++)
#pragma unroll
                    for (int j = 0; j < 4; j++) acc[m][f][j] = 0.f;

#pragma unroll 1
            for (int k = 0; k < 9; k++) {
                MBAR_WAIT(sb + SMQ + stage*16, (unsigned)ph);
                CP_WAIT0();
                asm volatile("bar.sync 1, 256;" ::: "memory");

                {
                    int kn = (k == 8) ? 0 : k + 1;
                    unsigned dst = sb + SMBR + (unsigned)(bs ^ 1)*16384 + (unsigned)ci*64;
                    const char* src = (const char*)g_wB + kn*16384 + ci*64;
#pragma unroll
                    for (int j = 0; j < 4; j++) CP_ASYNC16(dst + j*16, src + j*16);
                    CP_COMMIT();
                }

                const unsigned aH = sb + SMA + stage*32768;
                const unsigned aL = aH + 16384;
                const unsigned bH = sb + SMBR + (unsigned)bs*16384;
                const unsigned bL = bH + 8192;
#pragma unroll
                for (int kc = 0; kc < 4; kc++) {
                    unsigned ai0 = (a_row0 + kc*32) ^ a_swz;
                    unsigned ai1 = (a_row1 + kc*32) ^ a_swz;
                    unsigned a0h0,a0h1,a0h2,a0h3, a0l0,a0l1,a0l2,a0l3;
                    unsigned a1h0,a1h1,a1h2,a1h3, a1l0,a1l1,a1l2,a1l3;
                    ldsm_x4(a0h0,a0h1,a0h2,a0h3, aH + ai0);
                    ldsm_x4(a0l0,a0l1,a0l2,a0l3, aL + ai0);
                    ldsm_x4(a1h0,a1h1,a1h2,a1h3, aH + ai1);
                    ldsm_x4(a1l0,a1l1,a1l2,a1l3, aL + ai1);
#pragma unroll
                    for (int nb = 0; nb < 2; nb++) {
                        unsigned blk = (unsigned)(kc*4 + oh*2 + nb)*512 + b_inner;
                        unsigned bh0,bh1,bh2,bh3, bl0,bl1,bl2,bl3;
                        ldsm_x4t(bh0,bh1,bh2,bh3, bH + blk);
                        ldsm_x4t(bl0,bl1,bl2,bl3, bL + blk);
                        mma16816(acc[0][nb*2+0], a0h0,a0h1,a0h2,a0h3, bh0,bh1);
                        mma16816(acc[0][nb*2+1], a0h0,a0h1,a0h2,a0h3, bh2,bh3);
                        mma16816(acc[0][nb*2+0], a0h0,a0h1,a0h2,a0h3, bl0,bl1);
                        mma16816(acc[0][nb*2+1], a0h0,a0h1,a0h2,a0h3, bl2,bl3);
                        mma16816(acc[0][nb*2+0], a0l0,a0l1,a0l2,a0l3, bh0,bh1);
                        mma16816(acc[0][nb*2+1], a0l0,a0l1,a0l2,a0l3, bh2,bh3);
                        mma16816(acc[1][nb*2+0], a1h0,a1h1,a1h2,a1h3, bh0,bh1);
                        mma16816(acc[1][nb*2+1], a1h0,a1h1,a1h2,a1h3, bh2,bh3);
                        mma16816(acc[1][nb*2+0], a1h0,a1h1,a1h2,a1h3, bl0,bl1);
                        mma16816(acc[1][nb*2+1], a1h0,a1h1,a1h2,a1h3, bl2,bl3);
                        mma16816(acc[1][nb*2+0], a1l0,a1l1,a1l2,a1l3, bh0,bh1);
                        mma16816(acc[1][nb*2+1], a1l0,a1l1,a1l2,a1l3, bh2,bh3);
                    }
                }
                MBAR_ARRIVE(sb + SMQ + stage*16 + 8);
                if (++stage == 2) { stage = 0; ph ^= 1; }
                bs ^= 1;
            }

            const int oc0 = oh*32 + 2*(lane & 3);
#pragma unroll
            for (int m = 0; m < 2; m++) {
                const int px = pxc*32 + m*16 + (lane >> 2);
#pragma unroll
                for (int f = 0; f < 4; f++) {
                    const int oc = oc0 + (f >> 1)*16 + (f & 1)*8;
                    float* p0 = out + ((size_t)(b*64 + oc))*HW + h*W + px;
                    p0[0]      = acc[m][f][0];
                    p0[HW]     = acc[m][f][1];
                    p0[8]      = acc[m][f][2];
                    p0[HW + 8] = acc[m][f][3];
                }
            }
        }
    }
}

// ---------------- launch ----------------
extern "C" void kernel_launch(void* const* d_in, const int* in_sizes, int n_in,
                              void* d_out, int out_size) {
    const float* x      = (const float*)d_in[0];
    const float* w_off  = (const float*)d_in[1];
    const float* b_off  = (const float*)d_in[2];
    const float* w_conv = (const float*)d_in[3];
    float* out = (float*)d_out;

    cudaFuncSetAttribute(k_offconv_tc, cudaFuncAttributeMaxDynamicSharedMemorySize, OB_TOT);
    cudaFuncSetAttribute(k_fused_ws,   cudaFuncAttributeMaxDynamicSharedMemorySize, SMTOT);

    dim3 tgrid(HW/32, C/32, BB);
    dim3 tblk(32, 8);
    k_transpose_in<<<tgrid, tblk>>>(x);
    k_wprep<<<(9*2*64*64 + 255)/256, 256>>>(w_conv);
    k_woffprep<<<(9*2*64*32 + 255)/256, 256>>>(w_off);
    k_offconv_tc<<<152, 512, OB_TOT>>>(b_off);
    k_fused_ws<<<152, 512, SMTOT>>>(out);
}

// round 15
// speedup vs baseline: 1.1052x; 1.0257x over previous
#include <cuda_runtime.h>
#include <cuda_bf16.h>
#include <math.h>

#define BB 8
#define C 64
#define H 128
#define W 128
#define HW (H*W)            // 16384
#define NPIX (BB*HW)        // 131072
#define CO_OFF 27
#define KIDX 576
#define NTILE 1024          // 128 px per tile (one image row)

typedef unsigned long long u64;

// ---------------- packed fp32x2 helpers ----------------
__device__ __forceinline__ u64 pk(float x, float y) {
    u64 r; asm("mov.b64 %0, {%1, %2};" : "=l"(r) : "f"(x), "f"(y)); return r;
}
__device__ __forceinline__ float2 upk(u64 a) {
    float2 f; asm("mov.b64 {%0, %1}, %2;" : "=f"(f.x), "=f"(f.y) : "l"(a)); return f;
}
__device__ __forceinline__ u64 ffma2(u64 a, u64 b, u64 c) {
    u64 d; asm("fma.rn.f32x2 %0, %1, %2, %3;" : "=l"(d) : "l"(a), "l"(b), "l"(c)); return d;
}
__device__ __forceinline__ u64 fmul2(u64 a, u64 b) {
    u64 d; asm("mul.rn.f32x2 %0, %1, %2;" : "=l"(d) : "l"(a), "l"(b)); return d;
}
// bf16x2 pack: x -> low half, y -> high half
__device__ __forceinline__ unsigned bf16x2_of(float x, float y) {
    unsigned r; asm("cvt.rn.satfinite.bf16x2.f32 %0, %1, %2;" : "=r"(r) : "f"(y), "f"(x)); return r;
}

// ---------------- mma.sync / ldmatrix (baseline PTX) ----------------
__device__ __forceinline__ void ldsm_x4(unsigned& r0, unsigned& r1, unsigned& r2, unsigned& r3,
                                        unsigned addr) {
    asm volatile("ldmatrix.sync.aligned.m8n8.x4.shared.b16 {%0,%1,%2,%3}, [%4];"
        : "=r"(r0), "=r"(r1), "=r"(r2), "=r"(r3) : "r"(addr));
}
__device__ __forceinline__ void ldsm_x4t(unsigned& r0, unsigned& r1, unsigned& r2, unsigned& r3,
                                         unsigned addr) {
    asm volatile("ldmatrix.sync.aligned.m8n8.x4.trans.shared.b16 {%0,%1,%2,%3}, [%4];"
        : "=r"(r0), "=r"(r1), "=r"(r2), "=r"(r3) : "r"(addr));
}
__device__ __forceinline__ void mma16816(float* c,
                                         unsigned a0, unsigned a1, unsigned a2, unsigned a3,
                                         unsigned b0, unsigned b1) {
    asm volatile(
        "mma.sync.aligned.m16n8k16.row.col.f32.bf16.bf16.f32 "
        "{%0,%1,%2,%3}, {%4,%5,%6,%7}, {%8,%9}, {%0,%1,%2,%3};"
        : "+f"(c[0]), "+f"(c[1]), "+f"(c[2]), "+f"(c[3])
        : "r"(a0), "r"(a1), "r"(a2), "r"(a3), "r"(b0), "r"(b1));
}
__device__ __forceinline__ unsigned smem_u32(const void* p) {
    unsigned a; asm("{ .reg .u64 t; cvta.to.shared.u64 t, %1; cvt.u32.u64 %0, t; }" : "=r"(a) : "l"(p));
    return a;
}
#define MBAR_INIT(mb, n) asm volatile("mbarrier.init.shared.b64 [%0], %1;" :: "r"(mb), "r"(n) : "memory")
#define MBAR_ARRIVE(mb)  asm volatile("mbarrier.arrive.shared.b64 _, [%0];" :: "r"(mb) : "memory")
#define MBAR_WAIT(mb, ph) do { \
    unsigned _mb = (mb), _ph = (ph), _done; \
    asm volatile("{ .reg .pred p; mbarrier.try_wait.parity.acquire.cta.shared::cta.b64 p, [%1], %2; selp.b32 %0, 1, 0, p; }" \
        : "=r"(_done) : "r"(_mb), "r"(_ph) : "memory"); \
    if (!_done) { \
        asm volatile("{ .reg .pred P1; WL_%=: mbarrier.try_wait.parity.acquire.cta.shared::cta.b64 P1, [%0], %1, 0x989680; @P1 bra.uni WD_%=; bra.uni WL_%=; WD_%=: }" \
            :: "r"(_mb), "r"(_ph) : "memory"); \
    } } while (0)
#define CP_ASYNC16(dst, src) \
    asm volatile("cp.async.ca.shared.global [%0], [%1], 16;" :: "r"(dst), "l"(src) : "memory")
#define CP_COMMIT()  asm volatile("cp.async.commit_group;" ::: "memory")
#define CP_WAIT0()   asm volatile("cp.async.wait_group 0;" ::: "memory")

// ---------------- scratch ----------------
__device__ float g_xT[NPIX*C];                            // x NHWC
__device__ float g_off[BB*CO_OFF*HW];                     // offset conv out
__device__ __align__(16) unsigned short g_wB[9*2*64*64];  // w_conv hi/lo ldmatrix blocks
__device__ __align__(16) unsigned short g_wOB[9*2*64*32]; // w_off hi/lo ldmatrix blocks (N pad 32)

// ---------------- NCHW -> NHWC transpose of x ----------------
__global__ void k_transpose_in(const float* __restrict__ x) {
    __shared__ float tile[32][33];
    int b  = blockIdx.z;
    int c0 = blockIdx.y * 32;
    int p0 = blockIdx.x * 32;
    int tx = threadIdx.x, ty = threadIdx.y;
#pragma unroll
    for (int i = 0; i < 4; i++)
        tile[ty + 8*i][tx] = x[(b*C + c0 + ty + 8*i)*HW + p0 + tx];
    __syncthreads();
#pragma unroll
    for (int i = 0; i < 4; i++)
        g_xT[(b*HW + p0 + ty + 8*i)*C + c0 + tx] = tile[tx][ty + 8*i];
}

// ---------------- prep: w_conv -> bf16 hi/lo ldmatrix blocks ----------------
__global__ void k_wprep(const float* __restrict__ w_conv) {
    int i = blockIdx.x * blockDim.x + threadIdx.x;
    if (i >= 9*2*64*64) return;
    int o  = i & 63;
    int ch = (i >> 6) & 63;
    int hl = (i >> 12) & 1;
    int k  = i >> 13;
    float w = w_conv[o*KIDX + ch*9 + k];
    __nv_bfloat16 hi = __float2bfloat16(w);
    unsigned short val;
    if (hl == 0) {
        val = *(unsigned short*)&hi;
    } else {
        float fhi = __bfloat162float(hi);
        __nv_bfloat16 lo = __float2bfloat16(w - fhi);
        val = *(unsigned short*)&lo;
    }
    unsigned block = (unsigned)(((k*2 + hl)*16) + (ch >> 4)*4 + (o >> 4));
    unsigned inner = (unsigned)((ch & 15)*32 + (o & 15)*2);
    inner ^= ((inner >> 7) & 1) << 4;
    *(unsigned short*)((char*)g_wB + block*512 + inner) = val;
}

// ---------------- prep: w_off -> bf16 hi/lo ldmatrix blocks (N=32 pad) ------
__global__ void k_woffprep(const float* __restrict__ w_off) {
    int i = blockIdx.x * blockDim.x + threadIdx.x;
    if (i >= 9*2*64*32) return;
    int co = i & 31;
    int ch = (i >> 5) & 63;
    int hl = (i >> 11) & 1;
    int t  = i >> 12;
    float w = (co < CO_OFF) ? w_off[co*KIDX + ch*9 + t] : 0.f;
    __nv_bfloat16 hi = __float2bfloat16(w);
    unsigned short val;
    if (hl == 0) {
        val = *(unsigned short*)&hi;
    } else {
        float fhi = __bfloat162float(hi);
        __nv_bfloat16 lo = __float2bfloat16(w - fhi);
        val = *(unsigned short*)&lo;
    }
    unsigned block = (unsigned)((t*2 + hl)*8 + (ch >> 4)*2 + (co >> 4));
    unsigned inner = (unsigned)((ch & 15)*32 + (co & 15)*2);
    inner ^= ((inner >> 7) & 1) << 4;
    *(unsigned short*)((char*)g_wOB + block*512 + inner) = val;
}

// ---------------- offset conv via mma (software-pipelined) ------------------
// smem: [0..73728)        B blocks (9 taps x hl x [4 kc][2 n16] x 512B)
//       [73728..106496)   A hi, 2 buffers x 16384 B
//       [106496..139264)  A lo, 2 buffers x 16384 B
#define OB_B   0
#define OB_AH  73728
#define OB_AL  106496
#define OB_TOT 139264

__global__ __launch_bounds__(512, 1) void k_offconv_tc(const float* __restrict__ b_off) {
    extern __shared__ char sm[];
    const unsigned sb = smem_u32(sm);
    const int tid  = threadIdx.x;
    const int lane = tid & 31;
    const int warp = tid >> 5;

    // stage B once (73728 B)
    {
        const int4* src = (const int4*)g_wOB;
        int4* dst = (int4*)(sm + OB_B);
        for (int i = tid; i < 73728/16; i += 512) dst[i] = src[i];
    }
    __syncthreads();

    // A-build mapping: thread -> (px p, quarter q of 16 channels)
    const int p = tid >> 2;
    const int q = tid & 3;
    // MMA mapping: warp -> (16-px chunk, 16-o half)
    const int pxc = warp & 7;
    const int nh  = warp >> 3;
    const unsigned a_row = (unsigned)((pxc*16 + (lane & 15))*128 + (lane >> 4)*16);
    const unsigned a_swz = (unsigned)((lane & 7) << 4);
    unsigned b_inner = (unsigned)((lane & 15)*32 + (lane >> 4)*16);
    b_inner ^= ((b_inner >> 7) & 1) << 4;

    // bias for this lane's two output columns
    const int o0 = nh*16 + 2*(lane & 3);
    const int o1 = o0 + 8;
    float bia00 = (o0 < CO_OFF)     ? __ldg(b_off + o0)     : 0.f;
    float bia01 = (o0+1 < CO_OFF)   ? __ldg(b_off + o0 + 1) : 0.f;
    float bia10 = (o1 < CO_OFF)     ? __ldg(b_off + o1)     : 0.f;
    float bia11 = (o1+1 < CO_OFF)   ? __ldg(b_off + o1 + 1) : 0.f;

    for (int t = blockIdx.x; t < NTILE; t += gridDim.x) {
        const int b = t >> 7;
        const int h = t & 127;

        float acc[2][4];
#pragma unroll
        for (int n = 0; n < 2; n++)
#pragma unroll
            for (int j = 0; j < 4; j++) acc[n][j] = 0.f;

        // prologue: load tap-0 gather into registers
        float4 f[4];
        {
            const int srch = h - 1;
            const int srcw = p - 1;
            const bool valid = (srch >= 0) && (srch < H) && (srcw >= 0) && (srcw < W);
            if (valid) {
                const float4* src = (const float4*)(g_xT + ((size_t)(b*HW + srch*W + srcw))*64 + q*16);
#pragma unroll
                for (int j = 0; j < 4; j++) f[j] = src[j];
            } else {
#pragma unroll
                for (int j = 0; j < 4; j++) f[j] = make_float4(0.f, 0.f, 0.f, 0.f);
            }
        }

#pragma unroll 1
        for (int k = 0; k < 9; k++) {
            const int buf = k & 1;

            // ---- convert f (tap k) and STS into buf ----
            {
                uint4 hi2[2], lo2[2];
#pragma unroll
                for (int u = 0; u < 2; u++) {
                    float4 a = f[2*u], cc = f[2*u+1];
                    unsigned h0 = bf16x2_of(a.x, a.y);
                    unsigned h1 = bf16x2_of(a.z, a.w);
                    unsigned h2v = bf16x2_of(cc.x, cc.y);
                    unsigned h3 = bf16x2_of(cc.z, cc.w);
                    hi2[u] = make_uint4(h0, h1, h2v, h3);
                    lo2[u].x = bf16x2_of(a.x - __uint_as_float(h0 << 16),
                                         a.y - __uint_as_float(h0 & 0xffff0000u));
                    lo2[u].y = bf16x2_of(a.z - __uint_as_float(h1 << 16),
                                         a.w - __uint_as_float(h1 & 0xffff0000u));
                    lo2[u].z = bf16x2_of(cc.x - __uint_as_float(h2v << 16),
                                         cc.y - __uint_as_float(h2v & 0xffff0000u));
                    lo2[u].w = bf16x2_of(cc.z - __uint_as_float(h3 << 16),
                                         cc.w - __uint_as_float(h3 & 0xffff0000u));
                }
                unsigned base = (unsigned)(p*128 + q*32);
                unsigned u0 = (base)      ^ (unsigned)((p & 7) << 4);
                unsigned u1 = (base + 16) ^ (unsigned)((p & 7) << 4);
                char* ah = sm + OB_AH + buf*16384;
                char* al = sm + OB_AL + buf*16384;
                *(uint4*)(ah + u0) = hi2[0];
                *(uint4*)(ah + u1) = hi2[1];
                *(uint4*)(al + u0) = lo2[0];
                *(uint4*)(al + u1) = lo2[1];
            }

            // ---- prefetch tap k+1 gather (crosses barrier; hidden under MMA) ----
            if (k < 8) {
                const int kn = k + 1;
                const int srch = h + kn/3 - 1;
                const int srcw = p + kn%3 - 1;
                const bool valid = (srch >= 0) && (srch < H) && (srcw >= 0) && (srcw < W);
                if (valid) {
                    const float4* src = (const float4*)(g_xT + ((size_t)(b*HW + srch*W + srcw))*64 + q*16);
#pragma unroll
                    for (int j = 0; j < 4; j++) f[j] = src[j];
                } else {
#pragma unroll
                    for (int j = 0; j < 4; j++) f[j] = make_float4(0.f, 0.f, 0.f, 0.f);
                }
            }

            __syncthreads();      // buf[k&1] visible to all; MMA(k-?) ordering

            // ---- MMA for tap k ----
            const unsigned aH = sb + OB_AH + (unsigned)buf*16384;
            const unsigned aL = sb + OB_AL + (unsigned)buf*16384;
            const unsigned bBase  = sb + OB_B + (unsigned)(k*2)*4096;
            const unsigned bBaseL = bBase + 4096;
#pragma unroll
            for (int kc = 0; kc < 4; kc++) {
                unsigned ai = (a_row + kc*32) ^ a_swz;
                unsigned ah0, ah1, ah2, ah3, al0, al1, al2, al3;
                ldsm_x4(ah0, ah1, ah2, ah3, aH + ai);
                ldsm_x4(al0, al1, al2, al3, aL + ai);
                unsigned blk = (unsigned)(kc*2 + nh)*512 + b_inner;
                unsigned bh0, bh1, bh2, bh3, bl0, bl1, bl2, bl3;
                ldsm_x4t(bh0, bh1, bh2, bh3, bBase + blk);
                ldsm_x4t(bl0, bl1, bl2, bl3, bBaseL + blk);
                mma16816(acc[0], ah0, ah1, ah2, ah3, bh0, bh1);
                mma16816(acc[1], ah0, ah1, ah2, ah3, bh2, bh3);
                mma16816(acc[0], ah0, ah1, ah2, ah3, bl0, bl1);
                mma16816(acc[1], ah0, ah1, ah2, ah3, bl2, bl3);
                mma16816(acc[0], al0, al1, al2, al3, bh0, bh1);
                mma16816(acc[1], al0, al1, al2, al3, bh2, bh3);
            }
            // no trailing sync: next iteration writes the OTHER buffer;
            // its own __syncthreads orders reuse two taps later.
        }
        __syncthreads();          // protect buf0 across tiles

        // ---- epilogue: + bias, scatter NCHW into g_off ----
        const int px0 = pxc*16 + (lane >> 2);
        float* gb = g_off + (size_t)b*CO_OFF*HW + h*W;
        if (o0 < CO_OFF) {
            gb[o0*HW + px0]         = acc[0][0] + bia00;
            gb[o0*HW + px0 + 8]     = acc[0][2] + bia00;
        }
        if (o0 + 1 < CO_OFF) {
            gb[(o0+1)*HW + px0]     = acc[0][1] + bia01;
            gb[(o0+1)*HW + px0 + 8] = acc[0][3] + bia01;
        }
        if (o1 < CO_OFF) {
            gb[o1*HW + px0]         = acc[1][0] + bia10;
            gb[o1*HW + px0 + 8]     = acc[1][2] + bia10;
        }
        if (o1 + 1 < CO_OFF) {
            gb[(o1+1)*HW + px0]     = acc[1][1] + bia11;
            gb[(o1+1)*HW + px0 + 8] = acc[1][3] + bia11;
        }
    }
}

// ---------------- fused: 8 producer / 8 consumer warps (round-12 best) -----
#define SMA   0
#define SMBR  65536
#define SMP   98304
#define SMQ   102400
#define SMTOT 102464

__global__ __launch_bounds__(512, 1) void k_fused_ws(float* __restrict__ out) {
    extern __shared__ char sm[];
    const unsigned sb = smem_u32(sm);
    const int tid  = threadIdx.x;
    const int lane = tid & 31;
    const int warp = tid >> 5;

    if (tid == 0) {
        MBAR_INIT(sb + SMQ + 0,  256);
        MBAR_INIT(sb + SMQ + 8,  256);
        MBAR_INIT(sb + SMQ + 16, 256);
        MBAR_INIT(sb + SMQ + 24, 256);
    }
    __syncthreads();

    int stage = 0;

    if (warp < 8) {
        // ================= PRODUCER =================
        int ph = 1;
        const float2* xp2 = (const float2*)g_xT;
        const int wx = warp*16 + lane;
        const char* parp = sm + SMP + warp*512;

        for (int t = blockIdx.x; t < NTILE; t += gridDim.x) {
            const int b  = t >> 7;
            const int h  = t & 127;
            const int rb = b * HW;
            const int obase0 = b*CO_OFF*HW + h*W + wx;

            float no1 = 0.f, no2 = 0.f, nmv = 0.f;
            if (lane < 16) {
                no1 = __ldg(g_off + obase0);
                no2 = __ldg(g_off + obase0 +  9*HW);
                nmv = __ldg(g_off + obase0 + 18*HW);
            }

#pragma unroll 1
            for (int k = 0; k < 9; k++) {
                float o1 = no1, o2 = no2, mv = nmv;
                if (k < 8 && lane < 16) {
                    int ob = obase0 + (k+1)*HW;
                    no1 = __ldg(g_off + ob);
                    no2 = __ldg(g_off + ob +  9*HW);
                    nmv = __ldg(g_off + ob + 18*HW);
                }

                {
                    float mask = 1.f / (1.f + expf(-mv));
                    int kh = k / 3;
                    int kw = k - kh*3;
                    float px = o1 + (float)(wx + kw - 1);
                    float py = o2 + (float)(h + kh - 1);
                    float x0f = floorf(px), y0f = floorf(py);
                    int x0 = (int)x0f, y0 = (int)y0f;
                    float wx1 = px - x0f, wy1 = py - y0f;
                    float wx0 = 1.f - wx1, wy0 = 1.f - wy1;
                    float vx0 = (x0 >= 0  && x0     < W) ? 1.f : 0.f;
                    float vx1 = (x0 >= -1 && x0 + 1 < W) ? 1.f : 0.f;
                    float vy0 = (y0 >= 0  && y0     < H) ? 1.f : 0.f;
                    float vy1 = (y0 >= -1 && y0 + 1 < H) ? 1.f : 0.f;
                    int cx0 = min(max(x0,   0), W-1);
                    int cx1 = min(max(x0+1, 0), W-1);
                    int cy0 = min(max(y0,   0), H-1);
                    int cy1 = min(max(y0+1, 0), H-1);
                    float4 wt;
                    wt.x = wy0*wx0*mask*vy0*vx0;
                    wt.y = wy0*wx1*mask*vy0*vx1;
                    wt.z = wy1*wx0*mask*vy1*vx0;
                    wt.w = wy1*wx1*mask*vy1*vx1;
                    int4 ix;
                    ix.x = (rb + cy0*W + cx0) << 5;
                    ix.y = (rb + cy0*W + cx1) << 5;
                    ix.z = (rb + cy1*W + cx0) << 5;
                    ix.w = (rb + cy1*W + cx1) << 5;
                    if (lane < 16) {
                        *(float4*)((char*)parp + lane*32)      = wt;
                        *(int4*)  ((char*)parp + lane*32 + 16) = ix;
                    }
                }
                __syncwarp();

                float2 c[3][16];
#define P_ISSUE(bi, p4) { \
    _Pragma("unroll") \
    for (int j = 0; j < 4; j++) { \
        int pp = (p4)*4 + j; \
        int4 qi = *(const int4*)(parp + pp*32 + 16); \
        c[bi][j*4+0] = xp2[qi.x + lane]; \
        c[bi][j*4+1] = xp2[qi.y + lane]; \
        c[bi][j*4+2] = xp2[qi.z + lane]; \
        c[bi][j*4+3] = xp2[qi.w + lane]; \
    } }
#define P_COMBINE(bi, p4) { \
    _Pragma("unroll") \
    for (int j = 0; j < 4; j++) { \
        int pp = (p4)*4 + j; \
        float4 wt4 = *(const float4*)(parp + pp*32); \
        u64 r = fmul2(pk(wt4.x, wt4.x), pk(c[bi][j*4+0].x, c[bi][j*4+0].y)); \
        r = ffma2(pk(wt4.y, wt4.y), pk(c[bi][j*4+1].x, c[bi][j*4+1].y), r); \
        r = ffma2(pk(wt4.z, wt4.z), pk(c[bi][j*4+2].x, c[bi][j*4+2].y), r); \
        r = ffma2(pk(wt4.w, wt4.w), pk(c[bi][j*4+3].x, c[bi][j*4+3].y), r); \
        float2 v = upk(r); \
        unsigned h2 = bf16x2_of(v.x, v.y); \
        float hx = __uint_as_float(h2 << 16); \
        float hy = __uint_as_float(h2 & 0xffff0000u); \
        unsigned l2 = bf16x2_of(v.x - hx, v.y - hy); \
        int pxt = warp*16 + pp; \
        unsigned boff = (unsigned)(pxt*128 + lane*4); \
        boff ^= (unsigned)((pxt & 7) << 4); \
        *(unsigned*)(aBufH + boff) = h2; \
        *(unsigned*)(aBufL + boff) = l2; \
    } }

                P_ISSUE(0, 0);
                P_ISSUE(1, 1);
                MBAR_WAIT(sb + SMQ + stage*16 + 8, (unsigned)ph);
                char* aBufH = sm + SMA + stage*32768;
                char* aBufL = aBufH + 16384;
                P_ISSUE(2, 2);
                P_COMBINE(0, 0);
                P_ISSUE(0, 3);
                P_COMBINE(1, 1);
                P_COMBINE(2, 2);
                P_COMBINE(0, 3);
#undef P_ISSUE
#undef P_COMBINE
                MBAR_ARRIVE(sb + SMQ + stage*16);
                if (++stage == 2) { stage = 0; ph ^= 1; }
            }
        }
    } else {
        // ================= CONSUMER =================
        int ph = 0;
        const int cw  = warp - 8;
        const int pxc = cw & 3;
        const int oh  = cw >> 2;
        const unsigned a_row0 = (unsigned)((pxc*32 + (lane & 15))*128 + (lane >> 4)*16);
        const unsigned a_row1 = a_row0 + 16*128;
        const unsigned a_swz  = (unsigned)((lane & 7) << 4);
        unsigned b_inner = (unsigned)((lane & 15)*32 + (lane >> 4)*16);
        b_inner ^= ((b_inner >> 7) & 1) << 4;

        const int ci = cw*32 + lane;
        int bs = 0;
        {
            unsigned dst = sb + SMBR + (unsigned)ci*64;
            const char* src = (const char*)g_wB + ci*64;
#pragma unroll
            for (int j = 0; j < 4; j++) CP_ASYNC16(dst + j*16, src + j*16);
            CP_COMMIT();
        }

        for (int t = blockIdx.x; t < NTILE; t += gridDim.x) {
            const int b = t >> 7;
            const int h = t & 127;

            float acc[2][4][4];
#pragma unroll
            for (int m = 0; m < 2; m++)
#pragma unroll
                for (int f = 0; f < 4; f++)
#pragma unroll
                    for (int j = 0; j < 4; j++) acc[m][f][j] = 0.f;

#pragma unroll 1
            for (int k = 0; k < 9; k++) {
                MBAR_WAIT(sb + SMQ + stage*16, (unsigned)ph);
                CP_WAIT0();
                asm volatile("bar.sync 1, 256;" ::: "memory");

                {
                    int kn = (k == 8) ? 0 : k + 1;
                    unsigned dst = sb + SMBR + (unsigned)(bs ^ 1)*16384 + (unsigned)ci*64;
                    const char* src = (const char*)g_wB + kn*16384 + ci*64;
#pragma unroll
                    for (int j = 0; j < 4; j++) CP_ASYNC16(dst + j*16, src + j*16);
                    CP_COMMIT();
                }

                const unsigned aH = sb + SMA + stage*32768;
                const unsigned aL = aH + 16384;
                const unsigned bH = sb + SMBR + (unsigned)bs*16384;
                const unsigned bL = bH + 8192;
#pragma unroll
                for (int kc = 0; kc < 4; kc++) {
                    unsigned ai0 = (a_row0 + kc*32) ^ a_swz;
                    unsigned ai1 = (a_row1 + kc*32) ^ a_swz;
                    unsigned a0h0,a0h1,a0h2,a0h3, a0l0,a0l1,a0l2,a0l3;
                    unsigned a1h0,a1h1,a1h2,a1h3, a1l0,a1l1,a1l2,a1l3;
                    ldsm_x4(a0h0,a0h1,a0h2,a0h3, aH + ai0);
                    ldsm_x4(a0l0,a0l1,a0l2,a0l3, aL + ai0);
                    ldsm_x4(a1h0,a1h1,a1h2,a1h3, aH + ai1);
                    ldsm_x4(a1l0,a1l1,a1l2,a1l3, aL + ai1);
#pragma unroll
                    for (int nb = 0; nb < 2; nb++) {
                        unsigned blk = (unsigned)(kc*4 + oh*2 + nb)*512 + b_inner;
                        unsigned bh0,bh1,bh2,bh3, bl0,bl1,bl2,bl3;
                        ldsm_x4t(bh0,bh1,bh2,bh3, bH + blk);
                        ldsm_x4t(bl0,bl1,bl2,bl3, bL + blk);
                        mma16816(acc[0][nb*2+0], a0h0,a0h1,a0h2,a0h3, bh0,bh1);
                        mma16816(acc[0][nb*2+1], a0h0,a0h1,a0h2,a0h3, bh2,bh3);
                        mma16816(acc[0][nb*2+0], a0h0,a0h1,a0h2,a0h3, bl0,bl1);
                        mma16816(acc[0][nb*2+1], a0h0,a0h1,a0h2,a0h3, bl2,bl3);
                        mma16816(acc[0][nb*2+0], a0l0,a0l1,a0l2,a0l3, bh0,bh1);
                        mma16816(acc[0][nb*2+1], a0l0,a0l1,a0l2,a0l3, bh2,bh3);
                        mma16816(acc[1][nb*2+0], a1h0,a1h1,a1h2,a1h3, bh0,bh1);
                        mma16816(acc[1][nb*2+1], a1h0,a1h1,a1h2,a1h3, bh2,bh3);
                        mma16816(acc[1][nb*2+0], a1h0,a1h1,a1h2,a1h3, bl0,bl1);
                        mma16816(acc[1][nb*2+1], a1h0,a1h1,a1h2,a1h3, bl2,bl3);
                        mma16816(acc[1][nb*2+0], a1l0,a1l1,a1l2,a1l3, bh0,bh1);
                        mma16816(acc[1][nb*2+1], a1l0,a1l1,a1l2,a1l3, bh2,bh3);
                    }
                }
                MBAR_ARRIVE(sb + SMQ + stage*16 + 8);
                if (++stage == 2) { stage = 0; ph ^= 1; }
                bs ^= 1;
            }

            const int oc0 = oh*32 + 2*(lane & 3);
#pragma unroll
            for (int m = 0; m < 2; m++) {
                const int px = pxc*32 + m*16 + (lane >> 2);
#pragma unroll
                for (int f = 0; f < 4; f++) {
                    const int oc = oc0 + (f >> 1)*16 + (f & 1)*8;
                    float* p0 = out + ((size_t)(b*64 + oc))*HW + h*W + px;
                    p0[0]      = acc[m][f][0];
                    p0[HW]     = acc[m][f][1];
                    p0[8]      = acc[m][f][2];
                    p0[HW + 8] = acc[m][f][3];
                }
            }
        }
    }
}

// ---------------- launch ----------------
extern "C" void kernel_launch(void* const* d_in, const int* in_sizes, int n_in,
                              void* d_out, int out_size) {
    const float* x      = (const float*)d_in[0];
    const float* w_off  = (const float*)d_in[1];
    const float* b_off  = (const float*)d_in[2];
    const float* w_conv = (const float*)d_in[3];
    float* out = (float*)d_out;

    cudaFuncSetAttribute(k_offconv_tc, cudaFuncAttributeMaxDynamicSharedMemorySize, OB_TOT);
    cudaFuncSetAttribute(k_fused_ws,   cudaFuncAttributeMaxDynamicSharedMemorySize, SMTOT);

    dim3 tgrid(HW/32, C/32, BB);
    dim3 tblk(32, 8);
    k_transpose_in<<<tgrid, tblk>>>(x);
    k_wprep<<<(9*2*64*64 + 255)/256, 256>>>(w_conv);
    k_woffprep<<<(9*2*64*32 + 255)/256, 256>>>(w_off);
    k_offconv_tc<<<152, 512, OB_TOT>>>(b_off);
    k_fused_ws<<<152, 512, SMTOT>>>(out);
}

// round 16
// speedup vs baseline: 1.1995x; 1.0854x over previous
#include <cuda_runtime.h>
#include <cuda_bf16.h>
#include <math.h>

#define BB 8
#define C 64
#define H 128
#define W 128
#define HW (H*W)            // 16384
#define NPIX (BB*HW)        // 131072
#define CO_OFF 27
#define KIDX 576
#define NTILE 1024          // 128 px per tile (one image row)

typedef unsigned long long u64;

// ---------------- packed fp32x2 helpers ----------------
__device__ __forceinline__ u64 pk(float x, float y) {
    u64 r; asm("mov.b64 %0, {%1, %2};" : "=l"(r) : "f"(x), "f"(y)); return r;
}
__device__ __forceinline__ float2 upk(u64 a) {
    float2 f; asm("mov.b64 {%0, %1}, %2;" : "=f"(f.x), "=f"(f.y) : "l"(a)); return f;
}
__device__ __forceinline__ u64 ffma2(u64 a, u64 b, u64 c) {
    u64 d; asm("fma.rn.f32x2 %0, %1, %2, %3;" : "=l"(d) : "l"(a), "l"(b), "l"(c)); return d;
}
__device__ __forceinline__ u64 fmul2(u64 a, u64 b) {
    u64 d; asm("mul.rn.f32x2 %0, %1, %2;" : "=l"(d) : "l"(a), "l"(b)); return d;
}
// bf16x2 pack: x -> low half, y -> high half
__device__ __forceinline__ unsigned bf16x2_of(float x, float y) {
    unsigned r; asm("cvt.rn.satfinite.bf16x2.f32 %0, %1, %2;" : "=r"(r) : "f"(y), "f"(x)); return r;
}

// ---------------- mma.sync / ldmatrix (baseline PTX) ----------------
__device__ __forceinline__ void ldsm_x4(unsigned& r0, unsigned& r1, unsigned& r2, unsigned& r3,
                                        unsigned addr) {
    asm volatile("ldmatrix.sync.aligned.m8n8.x4.shared.b16 {%0,%1,%2,%3}, [%4];"
        : "=r"(r0), "=r"(r1), "=r"(r2), "=r"(r3) : "r"(addr));
}
__device__ __forceinline__ void ldsm_x4t(unsigned& r0, unsigned& r1, unsigned& r2, unsigned& r3,
                                         unsigned addr) {
    asm volatile("ldmatrix.sync.aligned.m8n8.x4.trans.shared.b16 {%0,%1,%2,%3}, [%4];"
        : "=r"(r0), "=r"(r1), "=r"(r2), "=r"(r3) : "r"(addr));
}
__device__ __forceinline__ void mma16816(float* c,
                                         unsigned a0, unsigned a1, unsigned a2, unsigned a3,
                                         unsigned b0, unsigned b1) {
    asm volatile(
        "mma.sync.aligned.m16n8k16.row.col.f32.bf16.bf16.f32 "
        "{%0,%1,%2,%3}, {%4,%5,%6,%7}, {%8,%9}, {%0,%1,%2,%3};"
        : "+f"(c[0]), "+f"(c[1]), "+f"(c[2]), "+f"(c[3])
        : "r"(a0), "r"(a1), "r"(a2), "r"(a3), "r"(b0), "r"(b1));
}
__device__ __forceinline__ unsigned smem_u32(const void* p) {
    unsigned a; asm("{ .reg .u64 t; cvta.to.shared.u64 t, %1; cvt.u32.u64 %0, t; }" : "=r"(a) : "l"(p));
    return a;
}
#define MBAR_INIT(mb, n) asm volatile("mbarrier.init.shared.b64 [%0], %1;" :: "r"(mb), "r"(n) : "memory")
#define MBAR_ARRIVE(mb)  asm volatile("mbarrier.arrive.shared.b64 _, [%0];" :: "r"(mb) : "memory")
#define MBAR_WAIT(mb, ph) do { \
    unsigned _mb = (mb), _ph = (ph), _done; \
    asm volatile("{ .reg .pred p; mbarrier.try_wait.parity.acquire.cta.shared::cta.b64 p, [%1], %2; selp.b32 %0, 1, 0, p; }" \
        : "=r"(_done) : "r"(_mb), "r"(_ph) : "memory"); \
    if (!_done) { \
        asm volatile("{ .reg .pred P1; WL_%=: mbarrier.try_wait.parity.acquire.cta.shared::cta.b64 P1, [%0], %1, 0x989680; @P1 bra.uni WD_%=; bra.uni WL_%=; WD_%=: }" \
            :: "r"(_mb), "r"(_ph) : "memory"); \
    } } while (0)
#define CP_ASYNC16(dst, src) \
    asm volatile("cp.async.ca.shared.global [%0], [%1], 16;" :: "r"(dst), "l"(src) : "memory")
#define CP_COMMIT()  asm volatile("cp.async.commit_group;" ::: "memory")
#define CP_WAIT0()   asm volatile("cp.async.wait_group 0;" ::: "memory")

// ---------------- scratch ----------------
__device__ float g_xT[NPIX*C];                            // x NHWC
__device__ float g_off[BB*CO_OFF*HW];                     // offset conv out
__device__ __align__(16) unsigned short g_wB[9*2*64*64];  // w_conv hi/lo ldmatrix blocks
__device__ __align__(16) unsigned short g_wOB[9*2*64*32]; // w_off hi/lo ldmatrix blocks (N pad 32)

// ---------------- NCHW -> NHWC transpose of x ----------------
__global__ void k_transpose_in(const float* __restrict__ x) {
    __shared__ float tile[32][33];
    int b  = blockIdx.z;
    int c0 = blockIdx.y * 32;
    int p0 = blockIdx.x * 32;
    int tx = threadIdx.x, ty = threadIdx.y;
#pragma unroll
    for (int i = 0; i < 4; i++)
        tile[ty + 8*i][tx] = x[(b*C + c0 + ty + 8*i)*HW + p0 + tx];
    __syncthreads();
#pragma unroll
    for (int i = 0; i < 4; i++)
        g_xT[(b*HW + p0 + ty + 8*i)*C + c0 + tx] = tile[tx][ty + 8*i];
}

// ---------------- prep: w_conv -> bf16 hi/lo ldmatrix blocks ----------------
__global__ void k_wprep(const float* __restrict__ w_conv) {
    int i = blockIdx.x * blockDim.x + threadIdx.x;
    if (i >= 9*2*64*64) return;
    int o  = i & 63;
    int ch = (i >> 6) & 63;
    int hl = (i >> 12) & 1;
    int k  = i >> 13;
    float w = w_conv[o*KIDX + ch*9 + k];
    __nv_bfloat16 hi = __float2bfloat16(w);
    unsigned short val;
    if (hl == 0) {
        val = *(unsigned short*)&hi;
    } else {
        float fhi = __bfloat162float(hi);
        __nv_bfloat16 lo = __float2bfloat16(w - fhi);
        val = *(unsigned short*)&lo;
    }
    unsigned block = (unsigned)(((k*2 + hl)*16) + (ch >> 4)*4 + (o >> 4));
    unsigned inner = (unsigned)((ch & 15)*32 + (o & 15)*2);
    inner ^= ((inner >> 7) & 1) << 4;
    *(unsigned short*)((char*)g_wB + block*512 + inner) = val;
}

// ---------------- prep: w_off -> bf16 hi/lo ldmatrix blocks (N=32 pad) ------
__global__ void k_woffprep(const float* __restrict__ w_off) {
    int i = blockIdx.x * blockDim.x + threadIdx.x;
    if (i >= 9*2*64*32) return;
    int co = i & 31;
    int ch = (i >> 5) & 63;
    int hl = (i >> 11) & 1;
    int t  = i >> 12;
    float w = (co < CO_OFF) ? w_off[co*KIDX + ch*9 + t] : 0.f;
    __nv_bfloat16 hi = __float2bfloat16(w);
    unsigned short val;
    if (hl == 0) {
        val = *(unsigned short*)&hi;
    } else {
        float fhi = __bfloat162float(hi);
        __nv_bfloat16 lo = __float2bfloat16(w - fhi);
        val = *(unsigned short*)&lo;
    }
    unsigned block = (unsigned)((t*2 + hl)*8 + (ch >> 4)*2 + (co >> 4));
    unsigned inner = (unsigned)((ch & 15)*32 + (co & 15)*2);
    inner ^= ((inner >> 7) & 1) << 4;
    *(unsigned short*)((char*)g_wOB + block*512 + inner) = val;
}

// ---------------- offset conv via mma (pipelined + coalesced A-build) -------
// smem: [0..73728)        B blocks (9 taps x hl x [4 kc][2 n16] x 512B)
//       [73728..106496)   A hi, 2 buffers x 16384 B
//       [106496..139264)  A lo, 2 buffers x 16384 B
#define OB_B   0
#define OB_AH  73728
#define OB_AL  106496
#define OB_TOT 139264

__global__ __launch_bounds__(512, 1) void k_offconv_tc(const float* __restrict__ b_off) {
    extern __shared__ char sm[];
    const unsigned sb = smem_u32(sm);
    const int tid  = threadIdx.x;
    const int lane = tid & 31;
    const int warp = tid >> 5;

    // stage B once (73728 B)
    {
        const int4* src = (const int4*)g_wOB;
        int4* dst = (int4*)(sm + OB_B);
        for (int i = tid; i < 73728/16; i += 512) dst[i] = src[i];
    }
    __syncthreads();

    // A-build mapping (coalesced): thread handles float4 f4idx = warp*128 + j*32 + lane
    //   px_j = warp*8 + j*2 + (lane>>4), c4 = lane & 15 (16B unit within px row)
    const int c4   = lane & 15;
    const int pxh  = (warp << 3) + (lane >> 4);   // + j*2 per load

    // MMA mapping: warp -> (16-px chunk, 16-o half)
    const int pxc = warp & 7;
    const int nh  = warp >> 3;
    const unsigned a_row = (unsigned)((pxc*16 + (lane & 15))*128 + (lane >> 4)*16);
    const unsigned a_swz = (unsigned)((lane & 7) << 4);
    unsigned b_inner = (unsigned)((lane & 15)*32 + (lane >> 4)*16);
    b_inner ^= ((b_inner >> 7) & 1) << 4;

    // bias for this lane's two output columns
    const int o0 = nh*16 + 2*(lane & 3);
    const int o1 = o0 + 8;
    float bia00 = (o0 < CO_OFF)     ? __ldg(b_off + o0)     : 0.f;
    float bia01 = (o0+1 < CO_OFF)   ? __ldg(b_off + o0 + 1) : 0.f;
    float bia10 = (o1 < CO_OFF)     ? __ldg(b_off + o1)     : 0.f;
    float bia11 = (o1+1 < CO_OFF)   ? __ldg(b_off + o1 + 1) : 0.f;

    for (int t = blockIdx.x; t < NTILE; t += gridDim.x) {
        const int b = t >> 7;
        const int h = t & 127;

        float acc[2][4];
#pragma unroll
        for (int n = 0; n < 2; n++)
#pragma unroll
            for (int j = 0; j < 4; j++) acc[n][j] = 0.f;

        // prologue: load tap-0 (dy=-1, dx=-1) into registers, coalesced
        float4 f[4];
        {
            const int srch = h - 1;
            const float4* srow = (const float4*)g_xT + (size_t)(b*HW + srch*W)*16;
#pragma unroll
            for (int j = 0; j < 4; j++) {
                const int px = pxh + j*2;
                const int srcw = px - 1;
                const bool v = (srch >= 0) && (srcw >= 0) && (srcw < W);
                f[j] = v ? srow[srcw*16 + c4] : make_float4(0.f, 0.f, 0.f, 0.f);
            }
        }

#pragma unroll 1
        for (int k = 0; k < 9; k++) {
            const int buf = k & 1;

            // ---- convert f (tap k) and STS into buf (coalesced STS.64) ----
            {
                char* ah = sm + OB_AH + buf*16384;
                char* al = sm + OB_AL + buf*16384;
#pragma unroll
                for (int j = 0; j < 4; j++) {
                    const int px = pxh + j*2;
                    float4 a = f[j];
                    uint2 hi, lo;
                    hi.x = bf16x2_of(a.x, a.y);
                    hi.y = bf16x2_of(a.z, a.w);
                    lo.x = bf16x2_of(a.x - __uint_as_float(hi.x << 16),
                                     a.y - __uint_as_float(hi.x & 0xffff0000u));
                    lo.y = bf16x2_of(a.z - __uint_as_float(hi.y << 16),
                                     a.w - __uint_as_float(hi.y & 0xffff0000u));
                    unsigned off = (unsigned)(px*128 + c4*8);
                    off ^= (unsigned)((px & 7) << 4);
                    *(uint2*)(ah + off) = hi;
                    *(uint2*)(al + off) = lo;
                }
            }

            // ---- prefetch tap k+1 gather (hidden under barrier + MMA) ----
            if (k < 8) {
                const int kn = k + 1;
                const int dy = kn/3 - 1, dx = kn%3 - 1;
                const int srch = h + dy;
                const bool vh = (srch >= 0) && (srch < H);
                const float4* srow = (const float4*)g_xT + (size_t)(b*HW + srch*W)*16;
#pragma unroll
                for (int j = 0; j < 4; j++) {
                    const int px = pxh + j*2;
                    const int srcw = px + dx;
                    const bool v = vh && (srcw >= 0) && (srcw < W);
                    f[j] = v ? srow[srcw*16 + c4] : make_float4(0.f, 0.f, 0.f, 0.f);
                }
            }

            __syncthreads();      // buf[k&1] visible to all

            // ---- MMA for tap k ----
            const unsigned aH = sb + OB_AH + (unsigned)buf*16384;
            const unsigned aL = sb + OB_AL + (unsigned)buf*16384;
            const unsigned bBase  = sb + OB_B + (unsigned)(k*2)*4096;
            const unsigned bBaseL = bBase + 4096;
#pragma unroll
            for (int kc = 0; kc < 4; kc++) {
                unsigned ai = (a_row + kc*32) ^ a_swz;
                unsigned ah0, ah1, ah2, ah3, al0, al1, al2, al3;
                ldsm_x4(ah0, ah1, ah2, ah3, aH + ai);
                ldsm_x4(al0, al1, al2, al3, aL + ai);
                unsigned blk = (unsigned)(kc*2 + nh)*512 + b_inner;
                unsigned bh0, bh1, bh2, bh3, bl0, bl1, bl2, bl3;
                ldsm_x4t(bh0, bh1, bh2, bh3, bBase + blk);
                ldsm_x4t(bl0, bl1, bl2, bl3, bBaseL + blk);
                mma16816(acc[0], ah0, ah1, ah2, ah3, bh0, bh1);
                mma16816(acc[1], ah0, ah1, ah2, ah3, bh2, bh3);
                mma16816(acc[0], ah0, ah1, ah2, ah3, bl0, bl1);
                mma16816(acc[1], ah0, ah1, ah2, ah3, bl2, bl3);
                mma16816(acc[0], al0, al1, al2, al3, bh0, bh1);
                mma16816(acc[1], al0, al1, al2, al3, bh2, bh3);
            }
            // next iteration writes the OTHER buffer; its own sync orders reuse
        }
        __syncthreads();          // protect buf0 across tiles

        // ---- epilogue: + bias, scatter NCHW into g_off ----
        const int px0 = pxc*16 + (lane >> 2);
        float* gb = g_off + (size_t)b*CO_OFF*HW + h*W;
        if (o0 < CO_OFF) {
            gb[o0*HW + px0]         = acc[0][0] + bia00;
            gb[o0*HW + px0 + 8]     = acc[0][2] + bia00;
        }
        if (o0 + 1 < CO_OFF) {
            gb[(o0+1)*HW + px0]     = acc[0][1] + bia01;
            gb[(o0+1)*HW + px0 + 8] = acc[0][3] + bia01;
        }
        if (o1 < CO_OFF) {
            gb[o1*HW + px0]         = acc[1][0] + bia10;
            gb[o1*HW + px0 + 8]     = acc[1][2] + bia10;
        }
        if (o1 + 1 < CO_OFF) {
            gb[(o1+1)*HW + px0]     = acc[1][1] + bia11;
            gb[(o1+1)*HW + px0 + 8] = acc[1][3] + bia11;
        }
    }
}

// ---------------- fused: 8 producer / 8 consumer warps (round-12 best) -----
#define SMA   0
#define SMBR  65536
#define SMP   98304
#define SMQ   102400
#define SMTOT 102464

__global__ __launch_bounds__(512, 1) void k_fused_ws(float* __restrict__ out) {
    extern __shared__ char sm[];
    const unsigned sb = smem_u32(sm);
    const int tid  = threadIdx.x;
    const int lane = tid & 31;
    const int warp = tid >> 5;

    if (tid == 0) {
        MBAR_INIT(sb + SMQ + 0,  256);
        MBAR_INIT(sb + SMQ + 8,  256);
        MBAR_INIT(sb + SMQ + 16, 256);
        MBAR_INIT(sb + SMQ + 24, 256);
    }
    __syncthreads();

    int stage = 0;

    if (warp < 8) {
        // ================= PRODUCER =================
        int ph = 1;
        const float2* xp2 = (const float2*)g_xT;
        const int wx = warp*16 + lane;
        const char* parp = sm + SMP + warp*512;

        for (int t = blockIdx.x; t < NTILE; t += gridDim.x) {
            const int b  = t >> 7;
            const int h  = t & 127;
            const int rb = b * HW;
            const int obase0 = b*CO_OFF*HW + h*W + wx;

            float no1 = 0.f, no2 = 0.f, nmv = 0.f;
            if (lane < 16) {
                no1 = __ldg(g_off + obase0);
                no2 = __ldg(g_off + obase0 +  9*HW);
                nmv = __ldg(g_off + obase0 + 18*HW);
            }

#pragma unroll 1
            for (int k = 0; k < 9; k++) {
                float o1 = no1, o2 = no2, mv = nmv;
                if (k < 8 && lane < 16) {
                    int ob = obase0 + (k+1)*HW;
                    no1 = __ldg(g_off + ob);
                    no2 = __ldg(g_off + ob +  9*HW);
                    nmv = __ldg(g_off + ob + 18*HW);
                }

                {
                    float mask = 1.f / (1.f + expf(-mv));
                    int kh = k / 3;
                    int kw = k - kh*3;
                    float px = o1 + (float)(wx + kw - 1);
                    float py = o2 + (float)(h + kh - 1);
                    float x0f = floorf(px), y0f = floorf(py);
                    int x0 = (int)x0f, y0 = (int)y0f;
                    float wx1 = px - x0f, wy1 = py - y0f;
                    float wx0 = 1.f - wx1, wy0 = 1.f - wy1;
                    float vx0 = (x0 >= 0  && x0     < W) ? 1.f : 0.f;
                    float vx1 = (x0 >= -1 && x0 + 1 < W) ? 1.f : 0.f;
                    float vy0 = (y0 >= 0  && y0     < H) ? 1.f : 0.f;
                    float vy1 = (y0 >= -1 && y0 + 1 < H) ? 1.f : 0.f;
                    int cx0 = min(max(x0,   0), W-1);
                    int cx1 = min(max(x0+1, 0), W-1);
                    int cy0 = min(max(y0,   0), H-1);
                    int cy1 = min(max(y0+1, 0), H-1);
                    float4 wt;
                    wt.x = wy0*wx0*mask*vy0*vx0;
                    wt.y = wy0*wx1*mask*vy0*vx1;
                    wt.z = wy1*wx0*mask*vy1*vx0;
                    wt.w = wy1*wx1*mask*vy1*vx1;
                    int4 ix;
                    ix.x = (rb + cy0*W + cx0) << 5;
                    ix.y = (rb + cy0*W + cx1) << 5;
                    ix.z = (rb + cy1*W + cx0) << 5;
                    ix.w = (rb + cy1*W + cx1) << 5;
                    if (lane < 16) {
                        *(float4*)((char*)parp + lane*32)      = wt;
                        *(int4*)  ((char*)parp + lane*32 + 16) = ix;
                    }
                }
                __syncwarp();

                float2 c[3][16];
#define P_ISSUE(bi, p4) { \
    _Pragma("unroll") \
    for (int j = 0; j < 4; j++) { \
        int pp = (p4)*4 + j; \
        int4 qi = *(const int4*)(parp + pp*32 + 16); \
        c[bi][j*4+0] = xp2[qi.x + lane]; \
        c[bi][j*4+1] = xp2[qi.y + lane]; \
        c[bi][j*4+2] = xp2[qi.z + lane]; \
        c[bi][j*4+3] = xp2[qi.w + lane]; \
    } }
#define P_COMBINE(bi, p4) { \
    _Pragma("unroll") \
    for (int j = 0; j < 4; j++) { \
        int pp = (p4)*4 + j; \
        float4 wt4 = *(const float4*)(parp + pp*32); \
        u64 r = fmul2(pk(wt4.x, wt4.x), pk(c[bi][j*4+0].x, c[bi][j*4+0].y)); \
        r = ffma2(pk(wt4.y, wt4.y), pk(c[bi][j*4+1].x, c[bi][j*4+1].y), r); \
        r = ffma2(pk(wt4.z, wt4.z), pk(c[bi][j*4+2].x, c[bi][j*4+2].y), r); \
        r = ffma2(pk(wt4.w, wt4.w), pk(c[bi][j*4+3].x, c[bi][j*4+3].y), r); \
        float2 v = upk(r); \
        unsigned h2 = bf16x2_of(v.x, v.y); \
        float hx = __uint_as_float(h2 << 16); \
        float hy = __uint_as_float(h2 & 0xffff0000u); \
        unsigned l2 = bf16x2_of(v.x - hx, v.y - hy); \
        int pxt = warp*16 + pp; \
        unsigned boff = (unsigned)(pxt*128 + lane*4); \
        boff ^= (unsigned)((pxt & 7) << 4); \
        *(unsigned*)(aBufH + boff) = h2; \
        *(unsigned*)(aBufL + boff) = l2; \
    } }

                P_ISSUE(0, 0);
                P_ISSUE(1, 1);
                MBAR_WAIT(sb + SMQ + stage*16 + 8, (unsigned)ph);
                char* aBufH = sm + SMA + stage*32768;
                char* aBufL = aBufH + 16384;
                P_ISSUE(2, 2);
                P_COMBINE(0, 0);
                P_ISSUE(0, 3);
                P_COMBINE(1, 1);
                P_COMBINE(2, 2);
                P_COMBINE(0, 3);
#undef P_ISSUE
#undef P_COMBINE
                MBAR_ARRIVE(sb + SMQ + stage*16);
                if (++stage == 2) { stage = 0; ph ^= 1; }
            }
        }
    } else {
        // ================= CONSUMER =================
        int ph = 0;
        const int cw  = warp - 8;
        const int pxc = cw & 3;
        const int oh  = cw >> 2;
        const unsigned a_row0 = (unsigned)((pxc*32 + (lane & 15))*128 + (lane >> 4)*16);
        const unsigned a_row1 = a_row0 + 16*128;
        const unsigned a_swz  = (unsigned)((lane & 7) << 4);
        unsigned b_inner = (unsigned)((lane & 15)*32 + (lane >> 4)*16);
        b_inner ^= ((b_inner >> 7) & 1) << 4;

        const int ci = cw*32 + lane;
        int bs = 0;
        {
            unsigned dst = sb + SMBR + (unsigned)ci*64;
            const char* src = (const char*)g_wB + ci*64;
#pragma unroll
            for (int j = 0; j < 4; j++) CP_ASYNC16(dst + j*16, src + j*16);
            CP_COMMIT();
        }

        for (int t = blockIdx.x; t < NTILE; t += gridDim.x) {
            const int b = t >> 7;
            const int h = t & 127;

            float acc[2][4][4];
#pragma unroll
            for (int m = 0; m < 2; m++)
#pragma unroll
                for (int f = 0; f < 4; f++)
#pragma unroll
                    for (int j = 0; j < 4; j++) acc[m][f][j] = 0.f;

#pragma unroll 1
            for (int k = 0; k < 9; k++) {
                MBAR_WAIT(sb + SMQ + stage*16, (unsigned)ph);
                CP_WAIT0();
                asm volatile("bar.sync 1, 256;" ::: "memory");

                {
                    int kn = (k == 8) ? 0 : k + 1;
                    unsigned dst = sb + SMBR + (unsigned)(bs ^ 1)*16384 + (unsigned)ci*64;
                    const char* src = (const char*)g_wB + kn*16384 + ci*64;
#pragma unroll
                    for (int j = 0; j < 4; j++) CP_ASYNC16(dst + j*16, src + j*16);
                    CP_COMMIT();
                }

                const unsigned aH = sb + SMA + stage*32768;
                const unsigned aL = aH + 16384;
                const unsigned bH = sb + SMBR + (unsigned)bs*16384;
                const unsigned bL = bH + 8192;
#pragma unroll
                for (int kc = 0; kc < 4; kc++) {
                    unsigned ai0 = (a_row0 + kc*32) ^ a_swz;
                    unsigned ai1 = (a_row1 + kc*32) ^ a_swz;
                    unsigned a0h0,a0h1,a0h2,a0h3, a0l0,a0l1,a0l2,a0l3;
                    unsigned a1h0,a1h1,a1h2,a1h3, a1l0,a1l1,a1l2,a1l3;
                    ldsm_x4(a0h0,a0h1,a0h2,a0h3, aH + ai0);
                    ldsm_x4(a0l0,a0l1,a0l2,a0l3, aL + ai0);
                    ldsm_x4(a1h0,a1h1,a1h2,a1h3, aH + ai1);
                    ldsm_x4(a1l0,a1l1,a1l2,a1l3, aL + ai1);
#pragma unroll
                    for (int nb = 0; nb < 2; nb++) {
                        unsigned blk = (unsigned)(kc*4 + oh*2 + nb)*512 + b_inner;
                        unsigned bh0,bh1,bh2,bh3, bl0,bl1,bl2,bl3;
                        ldsm_x4t(bh0,bh1,bh2,bh3, bH + blk);
                        ldsm_x4t(bl0,bl1,bl2,bl3, bL + blk);
                        mma16816(acc[0][nb*2+0], a0h0,a0h1,a0h2,a0h3, bh0,bh1);
                        mma16816(acc[0][nb*2+1], a0h0,a0h1,a0h2,a0h3, bh2,bh3);
                        mma16816(acc[0][nb*2+0], a0h0,a0h1,a0h2,a0h3, bl0,bl1);
                        mma16816(acc[0][nb*2+1], a0h0,a0h1,a0h2,a0h3, bl2,bl3);
                        mma16816(acc[0][nb*2+0], a0l0,a0l1,a0l2,a0l3, bh0,bh1);
                        mma16816(acc[0][nb*2+1], a0l0,a0l1,a0l2,a0l3, bh2,bh3);
                        mma16816(acc[1][nb*2+0], a1h0,a1h1,a1h2,a1h3, bh0,bh1);
                        mma16816(acc[1][nb*2+1], a1h0,a1h1,a1h2,a1h3, bh2,bh3);
                        mma16816(acc[1][nb*2+0], a1h0,a1h1,a1h2,a1h3, bl0,bl1);
                        mma16816(acc[1][nb*2+1], a1h0,a1h1,a1h2,a1h3, bl2,bl3);
                        mma16816(acc[1][nb*2+0], a1l0,a1l1,a1l2,a1l3, bh0,bh1);
                        mma16816(acc[1][nb*2+1], a1l0,a1l1,a1l2,a1l3, bh2,bh3);
                    }
                }
                MBAR_ARRIVE(sb + SMQ + stage*16 + 8);
                if (++stage == 2) { stage = 0; ph ^= 1; }
                bs ^= 1;
            }

            const int oc0 = oh*32 + 2*(lane & 3);
#pragma unroll
            for (int m = 0; m < 2; m++) {
                const int px = pxc*32 + m*16 + (lane >> 2);
#pragma unroll
                for (int f = 0; f < 4; f++) {
                    const int oc = oc0 + (f >> 1)*16 + (f & 1)*8;
                    float* p0 = out + ((size_t)(b*64 + oc))*HW + h*W + px;
                    p0[0]      = acc[m][f][0];
                    p0[HW]     = acc[m][f][1];
                    p0[8]      = acc[m][f][2];
                    p0[HW + 8] = acc[m][f][3];
                }
            }
        }
    }
}

// ---------------- launch ----------------
extern "C" void kernel_launch(void* const* d_in, const int* in_sizes, int n_in,
                              void* d_out, int out_size) {
    const float* x      = (const float*)d_in[0];
    const float* w_off  = (const float*)d_in[1];
    const float* b_off  = (const float*)d_in[2];
    const float* w_conv = (const float*)d_in[3];
    float* out = (float*)d_out;

    cudaFuncSetAttribute(k_offconv_tc, cudaFuncAttributeMaxDynamicSharedMemorySize, OB_TOT);
    cudaFuncSetAttribute(k_fused_ws,   cudaFuncAttributeMaxDynamicSharedMemorySize, SMTOT);

    dim3 tgrid(HW/32, C/32, BB);
    dim3 tblk(32, 8);
    k_transpose_in<<<tgrid, tblk>>>(x);
    k_wprep<<<(9*2*64*64 + 255)/256, 256>>>(w_conv);
    k_woffprep<<<(9*2*64*32 + 255)/256, 256>>>(w_off);
    k_offconv_tc<<<152, 512, OB_TOT>>>(b_off);
    k_fused_ws<<<152, 512, SMTOT>>>(out);
}

// round 17
// speedup vs baseline: 1.2208x; 1.0177x over previous
#include <cuda_runtime.h>
#include <cuda_bf16.h>
#include <math.h>

#define BB 8
#define C 64
#define H 128
#define W 128
#define HW (H*W)            // 16384
#define NPIX (BB*HW)        // 131072
#define CO_OFF 27
#define KIDX 576
#define NTILE 1024          // 128 px per tile (one image row)

typedef unsigned long long u64;

// ---------------- packed fp32x2 helpers ----------------
__device__ __forceinline__ u64 pk(float x, float y) {
    u64 r; asm("mov.b64 %0, {%1, %2};" : "=l"(r) : "f"(x), "f"(y)); return r;
}
__device__ __forceinline__ float2 upk(u64 a) {
    float2 f; asm("mov.b64 {%0, %1}, %2;" : "=f"(f.x), "=f"(f.y) : "l"(a)); return f;
}
__device__ __forceinline__ u64 ffma2(u64 a, u64 b, u64 c) {
    u64 d; asm("fma.rn.f32x2 %0, %1, %2, %3;" : "=l"(d) : "l"(a), "l"(b), "l"(c)); return d;
}
__device__ __forceinline__ u64 fmul2(u64 a, u64 b) {
    u64 d; asm("mul.rn.f32x2 %0, %1, %2;" : "=l"(d) : "l"(a), "l"(b)); return d;
}
// bf16x2 pack: x -> low half, y -> high half
__device__ __forceinline__ unsigned bf16x2_of(float x, float y) {
    unsigned r; asm("cvt.rn.satfinite.bf16x2.f32 %0, %1, %2;" : "=r"(r) : "f"(y), "f"(x)); return r;
}

// ---------------- mma.sync / ldmatrix (baseline PTX) ----------------
__device__ __forceinline__ void ldsm_x4(unsigned& r0, unsigned& r1, unsigned& r2, unsigned& r3,
                                        unsigned addr) {
    asm volatile("ldmatrix.sync.aligned.m8n8.x4.shared.b16 {%0,%1,%2,%3}, [%4];"
        : "=r"(r0), "=r"(r1), "=r"(r2), "=r"(r3) : "r"(addr));
}
__device__ __forceinline__ void ldsm_x4t(unsigned& r0, unsigned& r1, unsigned& r2, unsigned& r3,
                                         unsigned addr) {
    asm volatile("ldmatrix.sync.aligned.m8n8.x4.trans.shared.b16 {%0,%1,%2,%3}, [%4];"
        : "=r"(r0), "=r"(r1), "=r"(r2), "=r"(r3) : "r"(addr));
}
__device__ __forceinline__ void mma16816(float* c,
                                         unsigned a0, unsigned a1, unsigned a2, unsigned a3,
                                         unsigned b0, unsigned b1) {
    asm volatile(
        "mma.sync.aligned.m16n8k16.row.col.f32.bf16.bf16.f32 "
        "{%0,%1,%2,%3}, {%4,%5,%6,%7}, {%8,%9}, {%0,%1,%2,%3};"
        : "+f"(c[0]), "+f"(c[1]), "+f"(c[2]), "+f"(c[3])
        : "r"(a0), "r"(a1), "r"(a2), "r"(a3), "r"(b0), "r"(b1));
}
__device__ __forceinline__ unsigned smem_u32(const void* p) {
    unsigned a; asm("{ .reg .u64 t; cvta.to.shared.u64 t, %1; cvt.u32.u64 %0, t; }" : "=r"(a) : "l"(p));
    return a;
}
#define MBAR_INIT(mb, n) asm volatile("mbarrier.init.shared.b64 [%0], %1;" :: "r"(mb), "r"(n) : "memory")
#define MBAR_ARRIVE(mb)  asm volatile("mbarrier.arrive.shared.b64 _, [%0];" :: "r"(mb) : "memory")
#define MBAR_WAIT(mb, ph) do { \
    unsigned _mb = (mb), _ph = (ph), _done; \
    asm volatile("{ .reg .pred p; mbarrier.try_wait.parity.acquire.cta.shared::cta.b64 p, [%1], %2; selp.b32 %0, 1, 0, p; }" \
        : "=r"(_done) : "r"(_mb), "r"(_ph) : "memory"); \
    if (!_done) { \
        asm volatile("{ .reg .pred P1; WL_%=: mbarrier.try_wait.parity.acquire.cta.shared::cta.b64 P1, [%0], %1, 0x989680; @P1 bra.uni WD_%=; bra.uni WL_%=; WD_%=: }" \
            :: "r"(_mb), "r"(_ph) : "memory"); \
    } } while (0)
#define CP_ASYNC16(dst, src) \
    asm volatile("cp.async.ca.shared.global [%0], [%1], 16;" :: "r"(dst), "l"(src) : "memory")
#define CP_COMMIT()  asm volatile("cp.async.commit_group;" ::: "memory")
#define CP_WAIT0()   asm volatile("cp.async.wait_group 0;" ::: "memory")

// ---------------- scratch ----------------
__device__ float g_xT[NPIX*C];                            // x NHWC
__device__ __align__(16) unsigned short g_wB[9*2*64*64];  // w_conv hi/lo ldmatrix blocks
__device__ __align__(16) unsigned short g_wOB[9*2*64*32]; // w_off hi/lo ldmatrix blocks

// ---------------- NCHW -> NHWC transpose of x ----------------
__global__ void k_transpose_in(const float* __restrict__ x) {
    __shared__ float tile[32][33];
    int b  = blockIdx.z;
    int c0 = blockIdx.y * 32;
    int p0 = blockIdx.x * 32;
    int tx = threadIdx.x, ty = threadIdx.y;
#pragma unroll
    for (int i = 0; i < 4; i++)
        tile[ty + 8*i][tx] = x[(b*C + c0 + ty + 8*i)*HW + p0 + tx];
    __syncthreads();
#pragma unroll
    for (int i = 0; i < 4; i++)
        g_xT[(b*HW + p0 + ty + 8*i)*C + c0 + tx] = tile[tx][ty + 8*i];
}

// ---------------- prep: w_conv -> bf16 hi/lo ldmatrix blocks ----------------
__global__ void k_wprep(const float* __restrict__ w_conv) {
    int i = blockIdx.x * blockDim.x + threadIdx.x;
    if (i >= 9*2*64*64) return;
    int o  = i & 63;
    int ch = (i >> 6) & 63;
    int hl = (i >> 12) & 1;
    int k  = i >> 13;
    float w = w_conv[o*KIDX + ch*9 + k];
    __nv_bfloat16 hi = __float2bfloat16(w);
    unsigned short val;
    if (hl == 0) {
        val = *(unsigned short*)&hi;
    } else {
        float fhi = __bfloat162float(hi);
        __nv_bfloat16 lo = __float2bfloat16(w - fhi);
        val = *(unsigned short*)&lo;
    }
    unsigned block = (unsigned)(((k*2 + hl)*16) + (ch >> 4)*4 + (o >> 4));
    unsigned inner = (unsigned)((ch & 15)*32 + (o & 15)*2);
    inner ^= ((inner >> 7) & 1) << 4;
    *(unsigned short*)((char*)g_wB + block*512 + inner) = val;
}

// ---------------- prep: w_off -> bf16 hi/lo ldmatrix blocks (N=32 pad) ------
__global__ void k_woffprep(const float* __restrict__ w_off) {
    int i = blockIdx.x * blockDim.x + threadIdx.x;
    if (i >= 9*2*64*32) return;
    int co = i & 31;
    int ch = (i >> 5) & 63;
    int hl = (i >> 11) & 1;
    int t  = i >> 12;
    float w = (co < CO_OFF) ? w_off[co*KIDX + ch*9 + t] : 0.f;
    __nv_bfloat16 hi = __float2bfloat16(w);
    unsigned short val;
    if (hl == 0) {
        val = *(unsigned short*)&hi;
    } else {
        float fhi = __bfloat162float(hi);
        __nv_bfloat16 lo = __float2bfloat16(w - fhi);
        val = *(unsigned short*)&lo;
    }
    unsigned block = (unsigned)((t*2 + hl)*8 + (ch >> 4)*2 + (co >> 4));
    unsigned inner = (unsigned)((ch & 15)*32 + (co & 15)*2);
    inner ^= ((inner >> 7) & 1) << 4;
    *(unsigned short*)((char*)g_wOB + block*512 + inner) = val;
}

// ---------------- merged kernel: per tile {offconv phase; fused phase} ------
// smem:
//   [0..65536)       A ring, 2 stages x (hi 16KB + lo 16KB)  (shared by phases)
//   [65536..98304)   wConv B ring, 2 slots x 16KB (cp.async)
//   [98304..114688)  wOff  B ring, 2 slots x 8KB  (cp.async)
//   [114688..128512) offsets: [27][128] floats (13824 B)
//   [128512..132608) params: 8 producer warps x 512B
//   [132608..132640) mbarriers
#define SM_A    0
#define SM_BC   65536
#define SM_BO   98304
#define SM_OFS  114688
#define SM_PAR  128512
#define SM_Q    132608
#define SMTOT   132672

__global__ __launch_bounds__(512, 1) void k_mega(const float* __restrict__ b_off,
                                                 float* __restrict__ out) {
    extern __shared__ char sm[];
    const unsigned sb = smem_u32(sm);
    const int tid  = threadIdx.x;
    const int lane = tid & 31;
    const int warp = tid >> 5;

    if (tid == 0) {
        MBAR_INIT(sb + SM_Q + 0,  256);   // full0
        MBAR_INIT(sb + SM_Q + 8,  256);   // empty0
        MBAR_INIT(sb + SM_Q + 16, 256);   // full1
        MBAR_INIT(sb + SM_Q + 24, 256);   // empty1
    }

    // ---- offconv-phase constants ----
    const int c4  = lane & 15;                  // A-build: 16B unit within px row
    const int pxh = (warp << 3) + (lane >> 4);  // A-build: base px
    const int opxc = warp & 7;                  // MMA: 16-px chunk
    const int onh  = warp >> 3;                 // MMA: 16-o half
    const unsigned oa_row = (unsigned)((opxc*16 + (lane & 15))*128 + (lane >> 4)*16);
    const unsigned a_swz  = (unsigned)((lane & 7) << 4);
    unsigned b_inner = (unsigned)((lane & 15)*32 + (lane >> 4)*16);
    b_inner ^= ((b_inner >> 7) & 1) << 4;
    const int o0 = onh*16 + 2*(lane & 3);
    const int o1 = o0 + 8;
    float bia00 = (o0 < CO_OFF)     ? __ldg(b_off + o0)     : 0.f;
    float bia01 = (o0+1 < CO_OFF)   ? __ldg(b_off + o0 + 1) : 0.f;
    float bia10 = (o1 < CO_OFF)     ? __ldg(b_off + o1)     : 0.f;
    float bia11 = (o1+1 < CO_OFF)   ? __ldg(b_off + o1 + 1) : 0.f;
    float* off_s = (float*)(sm + SM_OFS);

    // ---- fused-phase constants ----
    const int wx = warp*16 + lane;                         // producer px (lane<16)
    const char* parp = sm + SM_PAR + (warp & 7)*512;
    const int cw   = warp - 8;                             // consumer index
    const int fpxc = cw & 3;
    const int foh  = cw >> 2;
    const unsigned fa_row0 = (unsigned)((fpxc*32 + (lane & 15))*128 + (lane >> 4)*16);
    const unsigned fa_row1 = fa_row0 + 16*128;
    const int ci = cw*32 + lane;                           // consumer copy index

    // ---- prime rings: wOff tap0 slot0 (all threads), wConv tap0 slot0 ----
    CP_ASYNC16(sb + SM_BO + (unsigned)tid*16, (const char*)g_wOB + tid*16);
    if (warp >= 8) {
        unsigned dst = sb + SM_BC + (unsigned)ci*64;
        const char* src = (const char*)g_wB + ci*64;
#pragma unroll
        for (int j = 0; j < 4; j++) CP_ASYNC16(dst + j*16, src + j*16);
    }
    CP_COMMIT();
    __syncthreads();

    int stage = 0;
    int ph = (warp < 8) ? 1 : 0;
    int bo = 0;     // wOff slot
    int bs = 0;     // wConv slot (consumers)
    const float2* xp2 = (const float2*)g_xT;

    for (int t = blockIdx.x; t < NTILE; t += gridDim.x) {
        const int b = t >> 7;
        const int h = t & 127;
        const int rb = b * HW;

        // ================= PHASE 1: offset conv (all 16 warps) =============
        {
            float oacc[2][4];
#pragma unroll
            for (int n = 0; n < 2; n++)
#pragma unroll
                for (int j = 0; j < 4; j++) oacc[n][j] = 0.f;

            float4 f[4];
            {   // prologue gather tap 0 (dy=-1, dx=-1)
                const int srch = h - 1;
                const float4* srow = (const float4*)g_xT + (size_t)(rb + srch*W)*16;
#pragma unroll
                for (int j = 0; j < 4; j++) {
                    const int px = pxh + j*2;
                    const int srcw = px - 1;
                    const bool v = (srch >= 0) && (srcw >= 0) && (srcw < W);
                    f[j] = v ? srow[srcw*16 + c4] : make_float4(0.f, 0.f, 0.f, 0.f);
                }
            }

#pragma unroll 1
            for (int k = 0; k < 9; k++) {
                const int buf = k & 1;
                // convert + STS (coalesced)
                {
                    char* ah = sm + SM_A + buf*32768;
                    char* al = ah + 16384;
#pragma unroll
                    for (int j = 0; j < 4; j++) {
                        const int px = pxh + j*2;
                        float4 a = f[j];
                        uint2 hi, lo;
                        hi.x = bf16x2_of(a.x, a.y);
                        hi.y = bf16x2_of(a.z, a.w);
                        lo.x = bf16x2_of(a.x - __uint_as_float(hi.x << 16),
                                         a.y - __uint_as_float(hi.x & 0xffff0000u));
                        lo.y = bf16x2_of(a.z - __uint_as_float(hi.y << 16),
                                         a.w - __uint_as_float(hi.y & 0xffff0000u));
                        unsigned off = (unsigned)(px*128 + c4*8);
                        off ^= (unsigned)((px & 7) << 4);
                        *(uint2*)(ah + off) = hi;
                        *(uint2*)(al + off) = lo;
                    }
                }
                // prefetch tap k+1 gather
                if (k < 8) {
                    const int kn = k + 1;
                    const int dy = kn/3 - 1, dx = kn%3 - 1;
                    const int srch = h + dy;
                    const bool vh = (srch >= 0) && (srch < H);
                    const float4* srow = (const float4*)g_xT + (size_t)(rb + srch*W)*16;
#pragma unroll
                    for (int j = 0; j < 4; j++) {
                        const int px = pxh + j*2;
                        const int srcw = px + dx;
                        const bool v = vh && (srcw >= 0) && (srcw < W);
                        f[j] = v ? srow[srcw*16 + c4] : make_float4(0.f, 0.f, 0.f, 0.f);
                    }
                }
                CP_WAIT0();            // wOff tap k landed (own copies)
                __syncthreads();       // A buf + B slot visible to all

                // prefetch wOff next tap (wraps to next tile's tap 0)
                {
                    int kn = (k == 8) ? 0 : k + 1;
                    CP_ASYNC16(sb + SM_BO + (unsigned)(bo ^ 1)*8192 + (unsigned)tid*16,
                               (const char*)g_wOB + kn*8192 + tid*16);
                    CP_COMMIT();
                }

                // MMA tap k
                const unsigned aH = sb + SM_A + (unsigned)buf*32768;
                const unsigned aL = aH + 16384;
                const unsigned bBase  = sb + SM_BO + (unsigned)bo*8192;
                const unsigned bBaseL = bBase + 4096;
#pragma unroll
                for (int kc = 0; kc < 4; kc++) {
                    unsigned ai = (oa_row + kc*32) ^ a_swz;
                    unsigned ah0, ah1, ah2, ah3, al0, al1, al2, al3;
                    ldsm_x4(ah0, ah1, ah2, ah3, aH + ai);
                    ldsm_x4(al0, al1, al2, al3, aL + ai);
                    unsigned blk = (unsigned)(kc*2 + onh)*512 + b_inner;
                    unsigned bh0, bh1, bh2, bh3, bl0, bl1, bl2, bl3;
                    ldsm_x4t(bh0, bh1, bh2, bh3, bBase + blk);
                    ldsm_x4t(bl0, bl1, bl2, bl3, bBaseL + blk);
                    mma16816(oacc[0], ah0, ah1, ah2, ah3, bh0, bh1);
                    mma16816(oacc[1], ah0, ah1, ah2, ah3, bh2, bh3);
                    mma16816(oacc[0], ah0, ah1, ah2, ah3, bl0, bl1);
                    mma16816(oacc[1], ah0, ah1, ah2, ah3, bl2, bl3);
                    mma16816(oacc[0], al0, al1, al2, al3, bh0, bh1);
                    mma16816(oacc[1], al0, al1, al2, al3, bh2, bh3);
                }
                bo ^= 1;
            }

            // epilogue: offsets -> smem
            const int px0 = opxc*16 + (lane >> 2);
            if (o0 < CO_OFF) {
                off_s[o0*128 + px0]     = oacc[0][0] + bia00;
                off_s[o0*128 + px0 + 8] = oacc[0][2] + bia00;
            }
            if (o0 + 1 < CO_OFF) {
                off_s[(o0+1)*128 + px0]     = oacc[0][1] + bia01;
                off_s[(o0+1)*128 + px0 + 8] = oacc[0][3] + bia01;
            }
            if (o1 < CO_OFF) {
                off_s[o1*128 + px0]     = oacc[1][0] + bia10;
                off_s[o1*128 + px0 + 8] = oacc[1][2] + bia10;
            }
            if (o1 + 1 < CO_OFF) {
                off_s[(o1+1)*128 + px0]     = oacc[1][1] + bia11;
                off_s[(o1+1)*128 + px0 + 8] = oacc[1][3] + bia11;
            }
        }
        __syncthreads();   // off_s visible; all offconv MMAs done (A ring free)

        // ================= PHASE 2: fused deformable GEMM ==================
        if (warp < 8) {
            // ---- PRODUCER ----
#pragma unroll 1
            for (int k = 0; k < 9; k++) {
                float o1v = 0.f, o2v = 0.f, mvv = 0.f;
                if (lane < 16) {
                    o1v = off_s[k*128 + wx];
                    o2v = off_s[(9+k)*128 + wx];
                    mvv = off_s[(18+k)*128 + wx];
                }
                {
                    float mask = 1.f / (1.f + expf(-mvv));
                    int kh = k / 3;
                    int kw = k - kh*3;
                    float px = o1v + (float)(wx + kw - 1);
                    float py = o2v + (float)(h + kh - 1);
                    float x0f = floorf(px), y0f = floorf(py);
                    int x0 = (int)x0f, y0 = (int)y0f;
                    float wx1 = px - x0f, wy1 = py - y0f;
                    float wx0 = 1.f - wx1, wy0 = 1.f - wy1;
                    float vx0 = (x0 >= 0  && x0     < W) ? 1.f : 0.f;
                    float vx1 = (x0 >= -1 && x0 + 1 < W) ? 1.f : 0.f;
                    float vy0 = (y0 >= 0  && y0     < H) ? 1.f : 0.f;
                    float vy1 = (y0 >= -1 && y0 + 1 < H) ? 1.f : 0.f;
                    int cx0 = min(max(x0,   0), W-1);
                    int cx1 = min(max(x0+1, 0), W-1);
                    int cy0 = min(max(y0,   0), H-1);
                    int cy1 = min(max(y0+1, 0), H-1);
                    float4 wt;
                    wt.x = wy0*wx0*mask*vy0*vx0;
                    wt.y = wy0*wx1*mask*vy0*vx1;
                    wt.z = wy1*wx0*mask*vy1*vx0;
                    wt.w = wy1*wx1*mask*vy1*vx1;
                    int4 ix;
                    ix.x = (rb + cy0*W + cx0) << 5;
                    ix.y = (rb + cy0*W + cx1) << 5;
                    ix.z = (rb + cy1*W + cx0) << 5;
                    ix.w = (rb + cy1*W + cx1) << 5;
                    if (lane < 16) {
                        *(float4*)((char*)parp + lane*32)      = wt;
                        *(int4*)  ((char*)parp + lane*32 + 16) = ix;
                    }
                }
                __syncwarp();

                float2 c[3][16];
#define P_ISSUE(bi, p4) { \
    _Pragma("unroll") \
    for (int j = 0; j < 4; j++) { \
        int pp = (p4)*4 + j; \
        int4 qi = *(const int4*)(parp + pp*32 + 16); \
        c[bi][j*4+0] = xp2[qi.x + lane]; \
        c[bi][j*4+1] = xp2[qi.y + lane]; \
        c[bi][j*4+2] = xp2[qi.z + lane]; \
        c[bi][j*4+3] = xp2[qi.w + lane]; \
    } }
#define P_COMBINE(bi, p4) { \
    _Pragma("unroll") \
    for (int j = 0; j < 4; j++) { \
        int pp = (p4)*4 + j; \
        float4 wt4 = *(const float4*)(parp + pp*32); \
        u64 r = fmul2(pk(wt4.x, wt4.x), pk(c[bi][j*4+0].x, c[bi][j*4+0].y)); \
        r = ffma2(pk(wt4.y, wt4.y), pk(c[bi][j*4+1].x, c[bi][j*4+1].y), r); \
        r = ffma2(pk(wt4.z, wt4.z), pk(c[bi][j*4+2].x, c[bi][j*4+2].y), r); \
        r = ffma2(pk(wt4.w, wt4.w), pk(c[bi][j*4+3].x, c[bi][j*4+3].y), r); \
        float2 v = upk(r); \
        unsigned h2 = bf16x2_of(v.x, v.y); \
        float hx = __uint_as_float(h2 << 16); \
        float hy = __uint_as_float(h2 & 0xffff0000u); \
        unsigned l2 = bf16x2_of(v.x - hx, v.y - hy); \
        int pxt = warp*16 + pp; \
        unsigned boff = (unsigned)(pxt*128 + lane*4); \
        boff ^= (unsigned)((pxt & 7) << 4); \
        *(unsigned*)(aBufH + boff) = h2; \
        *(unsigned*)(aBufL + boff) = l2; \
    } }

                P_ISSUE(0, 0);
                P_ISSUE(1, 1);
                MBAR_WAIT(sb + SM_Q + stage*16 + 8, (unsigned)ph);
                char* aBufH = sm + SM_A + stage*32768;
                char* aBufL = aBufH + 16384;
                P_ISSUE(2, 2);
                P_COMBINE(0, 0);
                P_ISSUE(0, 3);
                P_COMBINE(1, 1);
                P_COMBINE(2, 2);
                P_COMBINE(0, 3);
#undef P_ISSUE
#undef P_COMBINE
                MBAR_ARRIVE(sb + SM_Q + stage*16);
                if (++stage == 2) { stage = 0; ph ^= 1; }
            }
        } else {
            // ---- CONSUMER ----
            float acc[2][4][4];
#pragma unroll
            for (int m = 0; m < 2; m++)
#pragma unroll
                for (int fj = 0; fj < 4; fj++)
#pragma unroll
                    for (int j = 0; j < 4; j++) acc[m][fj][j] = 0.f;

#pragma unroll 1
            for (int k = 0; k < 9; k++) {
                MBAR_WAIT(sb + SM_Q + stage*16, (unsigned)ph);
                CP_WAIT0();
                asm volatile("bar.sync 1, 256;" ::: "memory");

                {   // prefetch next tap's wConv into other slot
                    int kn = (k == 8) ? 0 : k + 1;
                    unsigned dst = sb + SM_BC + (unsigned)(bs ^ 1)*16384 + (unsigned)ci*64;
                    const char* src = (const char*)g_wB + kn*16384 + ci*64;
#pragma unroll
                    for (int j = 0; j < 4; j++) CP_ASYNC16(dst + j*16, src + j*16);
                    CP_COMMIT();
                }

                const unsigned aH = sb + SM_A + (unsigned)stage*32768;
                const unsigned aL = aH + 16384;
                const unsigned bH = sb + SM_BC + (unsigned)bs*16384;
                const unsigned bL = bH + 8192;
#pragma unroll
                for (int kc = 0; kc < 4; kc++) {
                    unsigned ai0 = (fa_row0 + kc*32) ^ a_swz;
                    unsigned ai1 = (fa_row1 + kc*32) ^ a_swz;
                    unsigned a0h0,a0h1,a0h2,a0h3, a0l0,a0l1,a0l2,a0l3;
                    unsigned a1h0,a1h1,a1h2,a1h3, a1l0,a1l1,a1l2,a1l3;
                    ldsm_x4(a0h0,a0h1,a0h2,a0h3, aH + ai0);
                    ldsm_x4(a0l0,a0l1,a0l2,a0l3, aL + ai0);
                    ldsm_x4(a1h0,a1h1,a1h2,a1h3, aH + ai1);
                    ldsm_x4(a1l0,a1l1,a1l2,a1l3, aL + ai1);
#pragma unroll
                    for (int nb = 0; nb < 2; nb++) {
                        unsigned blk = (unsigned)(kc*4 + foh*2 + nb)*512 + b_inner;
                        unsigned bh0,bh1,bh2,bh3, bl0,bl1,bl2,bl3;
                        ldsm_x4t(bh0,bh1,bh2,bh3, bH + blk);
                        ldsm_x4t(bl0,bl1,bl2,bl3, bL + blk);
                        mma16816(acc[0][nb*2+0], a0h0,a0h1,a0h2,a0h3, bh0,bh1);
                        mma16816(acc[0][nb*2+1], a0h0,a0h1,a0h2,a0h3, bh2,bh3);
                        mma16816(acc[0][nb*2+0], a0h0,a0h1,a0h2,a0h3, bl0,bl1);
                        mma16816(acc[0][nb*2+1], a0h0,a0h1,a0h2,a0h3, bl2,bl3);
                        mma16816(acc[0][nb*2+0], a0l0,a0l1,a0l2,a0l3, bh0,bh1);
                        mma16816(acc[0][nb*2+1], a0l0,a0l1,a0l2,a0l3, bh2,bh3);
                        mma16816(acc[1][nb*2+0], a1h0,a1h1,a1h2,a1h3, bh0,bh1);
                        mma16816(acc[1][nb*2+1], a1h0,a1h1,a1h2,a1h3, bh2,bh3);
                        mma16816(acc[1][nb*2+0], a1h0,a1h1,a1h2,a1h3, bl0,bl1);
                        mma16816(acc[1][nb*2+1], a1h0,a1h1,a1h2,a1h3, bl2,bl3);
                        mma16816(acc[1][nb*2+0], a1l0,a1l1,a1l2,a1l3, bh0,bh1);
                        mma16816(acc[1][nb*2+1], a1l0,a1l1,a1l2,a1l3, bh2,bh3);
                    }
                }
                MBAR_ARRIVE(sb + SM_Q + stage*16 + 8);
                if (++stage == 2) { stage = 0; ph ^= 1; }
                bs ^= 1;
            }

            // epilogue: registers -> out directly in NCHW
            const int oc0 = foh*32 + 2*(lane & 3);
#pragma unroll
            for (int m = 0; m < 2; m++) {
                const int px = fpxc*32 + m*16 + (lane >> 2);
#pragma unroll
                for (int fj = 0; fj < 4; fj++) {
                    const int oc = oc0 + (fj >> 1)*16 + (fj & 1)*8;
                    float* p0 = out + ((size_t)(b*64 + oc))*HW + h*W + px;
                    p0[0]      = acc[m][fj][0];
                    p0[HW]     = acc[m][fj][1];
                    p0[8]      = acc[m][fj][2];
                    p0[HW + 8] = acc[m][fj][3];
                }
            }
        }
        __syncthreads();   // A ring + off_s reusable by next tile's offconv
    }
}

// ---------------- launch ----------------
extern "C" void kernel_launch(void* const* d_in, const int* in_sizes, int n_in,
                              void* d_out, int out_size) {
    const float* x      = (const float*)d_in[0];
    const float* w_off  = (const float*)d_in[1];
    const float* b_off  = (const float*)d_in[2];
    const float* w_conv = (const float*)d_in[3];
    float* out = (float*)d_out;

    cudaFuncSetAttribute(k_mega, cudaFuncAttributeMaxDynamicSharedMemorySize, SMTOT);

    dim3 tgrid(HW/32, C/32, BB);
    dim3 tblk(32, 8);
    k_transpose_in<<<tgrid, tblk>>>(x);
    k_wprep<<<(9*2*64*64 + 255)/256, 256>>>(w_conv);
    k_woffprep<<<(9*2*64*32 + 255)/256, 256>>>(w_off);
    k_mega<<<152, 512, SMTOT>>>(b_off, out);
}